// round 13
// baseline (speedup 1.0000x reference)
#include <cuda_runtime.h>
#include <cuda_bf16.h>
#include <math.h>

#define NA    900
#define NTEMP 600
#define ED    256
#define NC    6
#define NL    4
#define NP    13
#define NG    8
#define NLEARN 6
#define NDEC  6
#define ADIM  11
#define NCLS  10
#define WTOT  (NC*NL*NP*NG)   // 2496
#define NSEL  (NA-NTEMP)      // 300
#define NITEM (NL*NP*NC)      // 312
#define WSTR  313             // transposed softmax row stride

typedef unsigned long long ull;

// -------- output layout (flattened tuple, float32) --------
#define OFF_INST   0
#define OFF_ANCHOR (NA*ED)
#define OFF_CLS    (OFF_ANCHOR + NA*ADIM)
#define OFF_QT     (OFF_CLS + NA*NCLS)
#define OFF_TRACK  (OFF_QT + NA)
#define OFF_TMP    (OFF_TRACK + NA)

// -------- scratch --------
__device__ __align__(16) float g_instA[NA*ED];
__device__ __align__(16) float g_instB[NA*ED];
__device__ __align__(16) float g_anchorA[NA*ADIM];
__device__ __align__(16) float g_anchorB[NA*ADIM];
__device__ __align__(16) float g_W[NA*WTOT];
__device__ __align__(16) float g_cls[NA*NCLS];
__device__ __align__(16) float g_Wcomb[NDEC*ED*ED];
__device__ __align__(16) float g_bcomb[NDEC*ED];
__device__ __align__(16) float g_AWm[NDEC*12*WTOT];
__device__ int g_sel[NA];

__constant__ float c_FIX[7][3] = {
    {0.f,0.f,0.f},{0.5f,0.f,0.f},{-0.5f,0.f,0.f},
    {0.f,0.5f,0.f},{0.f,-0.5f,0.f},{0.f,0.f,0.5f},{0.f,0.f,-0.5f}};

// ---- f32x2 helpers ----
__device__ __forceinline__ ull pack2(float x, float y) {
    ull r;
    asm("mov.b64 %0, {%1, %2};" : "=l"(r) : "f"(x), "f"(y));
    return r;
}
__device__ __forceinline__ void unpack2(ull v, float& x, float& y) {
    asm("mov.b64 {%0, %1}, %2;" : "=f"(x), "=f"(y) : "l"(v));
}
__device__ __forceinline__ void ffma2(ull& acc, ull a, ull b) {
    asm("fma.rn.f32x2 %0, %1, %2, %0;" : "+l"(acc) : "l"(a), "l"(b));
}

// ===================== P1a: Wcomb = Wo @ Wf1 (per iter) ===================
__global__ void kP1a(const float* __restrict__ outp_w,
                     const float* __restrict__ ffn_w)
{
    int i = blockIdx.z;
    const float* A = outp_w + (size_t)i*ED*ED;
    const float* B = ffn_w + (size_t)i*2*ED*ED;
    float* C = g_Wcomb + (size_t)i*ED*ED;

    __shared__ __align__(16) float As[64][16];
    __shared__ __align__(16) float Bs[16][64];

    int tid = threadIdx.x;
    int tRow = tid >> 4, tCol = tid & 15;
    int m0 = blockIdx.y * 64, n0 = blockIdx.x * 64;
    int aRow = tid >> 2, aK4 = (tid & 3) * 4;
    int bRow = tid >> 4, bCol = (tid & 15) * 4;

    ull acc[4][2];
    #pragma unroll
    for (int r = 0; r < 4; r++) { acc[r][0] = 0ull; acc[r][1] = 0ull; }

    for (int k0 = 0; k0 < ED; k0 += 16) {
        *(float4*)&As[aRow][aK4] = *(const float4*)&A[(m0+aRow)*ED + k0 + aK4];
        *(float4*)&Bs[bRow][bCol] = *(const float4*)&B[(k0+bRow)*ED + n0 + bCol];
        __syncthreads();
        #pragma unroll
        for (int k = 0; k < 16; k++) {
            ull b0 = *(const ull*)&Bs[k][tCol*4 + 0];
            ull b1 = *(const ull*)&Bs[k][tCol*4 + 2];
            #pragma unroll
            for (int r = 0; r < 4; r++) {
                float a = As[tRow*4 + r][k];
                ull ad = pack2(a, a);
                ffma2(acc[r][0], ad, b0);
                ffma2(acc[r][1], ad, b1);
            }
        }
        __syncthreads();
    }
    #pragma unroll
    for (int r = 0; r < 4; r++) {
        float x0, y0, x1, y1;
        unpack2(acc[r][0], x0, y0);
        unpack2(acc[r][1], x1, y1);
        *(float4*)&C[(m0+tRow*4+r)*ED + n0 + tCol*4] = make_float4(x0, y0, x1, y1);
    }
}

// ===================== P1b: bcomb = bo@Wf1 + bf ===========================
__global__ void kP1b(const float* __restrict__ outp_b,
                     const float* __restrict__ ffn_w,
                     const float* __restrict__ ffn_b)
{
    int i = blockIdx.x;
    const float* bo = outp_b + (size_t)i*ED;
    const float* Wf = ffn_w + (size_t)i*2*ED*ED;
    const float* bf = ffn_b + (size_t)i*ED;
    int t = threadIdx.x;
    __shared__ float sbo[ED];
    sbo[t] = bo[t];
    __syncthreads();
    float s0 = 0.f, s1 = 0.f, s2 = 0.f, s3 = 0.f;
    for (int n = 0; n < ED; n += 4) {
        s0 += sbo[n+0] * Wf[(n+0)*ED + t];
        s1 += sbo[n+1] * Wf[(n+1)*ED + t];
        s2 += sbo[n+2] * Wf[(n+2)*ED + t];
        s3 += sbo[n+3] * Wf[(n+3)*ED + t];
    }
    g_bcomb[i*ED + t] = bf[t] + ((s0 + s1) + (s2 + s3));
}

// ===================== P2: AWm = [anchor_w;anchor_b] @ wfc ================
__global__ void kP2(const float* __restrict__ anchor_w,
                    const float* __restrict__ anchor_b,
                    const float* __restrict__ wfc_w)
{
    int i = blockIdx.y;
    int n0 = blockIdx.x * 96;
    const float* Wm = wfc_w + (size_t)i*ED*WTOT;
    float* dst = g_AWm + (size_t)i*12*WTOT;
    int t = threadIdx.x;

    __shared__ float sAw[12*ED];
    __shared__ float sT[32*96];

    for (int idx = t; idx < 11*ED; idx += 256) sAw[idx] = anchor_w[idx];
    for (int idx = t; idx < ED; idx += 256)    sAw[11*ED + idx] = anchor_b[idx];
    __syncthreads();

    float acc[5] = {0.f,0.f,0.f,0.f,0.f};
    for (int k0 = 0; k0 < ED; k0 += 32) {
        for (int idx = t; idx < 32*96; idx += 256) {
            int kk = idx / 96, nc = idx % 96;
            sT[idx] = Wm[(size_t)(k0+kk)*WTOT + n0 + nc];
        }
        __syncthreads();
        int slot = 0;
        for (int o = t; o < 12*96; o += 256, slot++) {
            int j = o / 96, nc = o % 96;
            float s = acc[slot];
            #pragma unroll 8
            for (int kk = 0; kk < 32; kk++)
                s += sAw[j*ED + k0 + kk] * sT[kk*96 + nc];
            acc[slot] = s;
        }
        __syncthreads();
    }
    int slot = 0;
    for (int o = t; o < 12*96; o += 256, slot++) {
        int j = o / 96, nc = o % 96;
        dst[(size_t)j*WTOT + n0 + nc] = acc[slot];
    }
}

// ===================== k2: wfc GEMM + rank-12 fold, ping-pong smem ========
#define BM 64
#define BN 96
#define BK 16
__global__ void k2_wfc_gemm(const float* __restrict__ instR,
                            const float* __restrict__ anchR,
                            const float* __restrict__ Wm,
                            const float* __restrict__ bias,
                            const float* __restrict__ AWm)
{
    __shared__ __align__(16) float As[2][BM][BK];
    __shared__ __align__(16) float Bs[2][BK][BN];
    __shared__ float sAnchT[BM][12];
    __shared__ __align__(8) float sAW[12][BN];

    int tid  = threadIdx.x;
    int tRow = tid >> 4, tCol = tid & 15;
    int m0 = blockIdx.y * BM, n0 = blockIdx.x * BN;

    for (int idx = tid; idx < BM*ADIM; idx += 256) {
        int r = idx / ADIM, j = idx % ADIM;
        int row = m0 + r;
        sAnchT[r][j] = (row < NA) ? anchR[row*ADIM + j] : 0.f;
    }
    for (int idx = tid; idx < 12*BN; idx += 256) {
        int j = idx / BN, nc = idx % BN;
        sAW[j][nc] = AWm[(size_t)j*WTOT + n0 + nc];
    }

    ull acc[4][3];
    #pragma unroll
    for (int i = 0; i < 4; i++)
        #pragma unroll
        for (int j = 0; j < 3; j++) acc[i][j] = 0ull;

    int aRow = tid >> 2;
    int aK4  = (tid & 3) * 4;
    int gm   = m0 + aRow;
    bool mok = (gm < NA);

    int bR[3], bC[3];
    #pragma unroll
    for (int it = 0; it < 3; it++) {
        int lin = tid + it*256;
        bR[it] = lin / 48;
        bC[it] = (lin % 48) * 2;
    }

    float4 avr = mok ? *(const float4*)&instR[gm*ED + aK4] : make_float4(0.f,0.f,0.f,0.f);
    float2 bvr[3];
    #pragma unroll
    for (int it = 0; it < 3; it++)
        bvr[it] = *(const float2*)&Wm[(size_t)bR[it]*WTOT + n0 + bC[it]];

    const int NT = ED / BK;   // 16
    for (int kt = 0; kt < NT; kt++) {
        int buf = kt & 1;
        // store tile kt (regs) -> buf
        *(float4*)&As[buf][aRow][aK4] = avr;
        #pragma unroll
        for (int it = 0; it < 3; it++)
            *(float2*)&Bs[buf][bR[it]][bC[it]] = bvr[it];
        __syncthreads();   // single barrier per stage

        // prefetch tile kt+1 into regs (overlaps compute)
        int k0n = (kt + 1) * BK;
        if (k0n < ED) {
            if (mok) avr = *(const float4*)&instR[gm*ED + k0n + aK4];
            #pragma unroll
            for (int it = 0; it < 3; it++)
                bvr[it] = *(const float2*)&Wm[(size_t)(k0n + bR[it])*WTOT + n0 + bC[it]];
        }

        #pragma unroll
        for (int k = 0; k < BK; k++) {
            ull b0 = *(const ull*)&Bs[buf][k][tCol*6 + 0];
            ull b1 = *(const ull*)&Bs[buf][k][tCol*6 + 2];
            ull b2 = *(const ull*)&Bs[buf][k][tCol*6 + 4];
            #pragma unroll
            for (int i = 0; i < 4; i++) {
                float a = As[buf][tRow*4 + i][k];
                ull ad = pack2(a, a);
                ffma2(acc[i][0], ad, b0);
                ffma2(acc[i][1], ad, b1);
                ffma2(acc[i][2], ad, b2);
            }
        }
        // no trailing sync: next stage writes the OTHER buffer; WAR separated
        // by the barrier in the following stage.
    }

    float2 bb[3];
    #pragma unroll
    for (int j = 0; j < 3; j++)
        bb[j] = *(const float2*)&bias[n0 + tCol*6 + 2*j];

    #pragma unroll
    for (int i = 0; i < 4; i++) {
        int lr = tRow*4 + i;
        int r = m0 + lr;
        if (r >= NA) continue;
        ull corr[3];
        #pragma unroll
        for (int j = 0; j < 3; j++)
            corr[j] = *(const ull*)&sAW[11][tCol*6 + 2*j];
        #pragma unroll
        for (int j = 0; j < ADIM; j++) {
            float a = sAnchT[lr][j];
            ull ad = pack2(a, a);
            ffma2(corr[0], ad, *(const ull*)&sAW[j][tCol*6 + 0]);
            ffma2(corr[1], ad, *(const ull*)&sAW[j][tCol*6 + 2]);
            ffma2(corr[2], ad, *(const ull*)&sAW[j][tCol*6 + 4]);
        }
        #pragma unroll
        for (int j = 0; j < 3; j++) {
            float x, y, cx, cy;
            unpack2(acc[i][j], x, y);
            unpack2(corr[j], cx, cy);
            float2 v = make_float2(x + cx + bb[j].x, y + cy + bb[j].y);
            *(float2*)&g_W[(size_t)r*WTOT + n0 + tCol*6 + 2*j] = v;
        }
    }
}

// ===================== k4: kps/proj + softmax + chunked aggregation =======
__global__ void k4_daf(const float* __restrict__ feature,
                       const int* __restrict__ ss,
                       const int* __restrict__ lsi,
                       int T,
                       float* __restrict__ feats_out,
                       const float* __restrict__ instR,
                       const float* __restrict__ anchR,
                       const float* __restrict__ kps_w,
                       const float* __restrict__ kps_b,
                       const float* __restrict__ l2i,
                       const float* __restrict__ image_wh)
{
    int a = blockIdx.x, t = threadIdx.x, g8 = t >> 5, lane = t & 31;

    __shared__ float sWt[NG*WSTR];
    __shared__ float sfeat[ED];
    __shared__ float sanchor[ADIM];
    __shared__ float spart[18][8];
    __shared__ float slearn[18];
    __shared__ float skp[NP][3];
    __shared__ float suv[NP*NC*2];
    __shared__ int   sh[12];
    __shared__ int   sValid[NITEM];
    __shared__ int   sWi[NITEM];
    __shared__ int4  sOff[NITEM];
    __shared__ float4 sCw[NITEM];
    __shared__ short sIdx[NITEM];
    __shared__ int   s_nv;
    __shared__ __align__(16) float4 sPart[4][64];

    for (int idx = t; idx < WTOT; idx += 256) {
        float v = g_W[(size_t)a*WTOT + idx];
        sWt[(idx & 7)*WSTR + (idx >> 3)] = v;
    }
    sfeat[t] = instR[a*ED + t];
    if (t < ADIM) sanchor[t] = anchR[a*ADIM + t];
    if (t < 8) sh[t]   = ss[t];
    if (t < 4) sh[8+t] = lsi[t];
    __syncthreads();

    {
        float* row = &sWt[g8*WSTR];
        float vals[10];
        float mx = -1e30f;
        int cnt = 0;
        for (int j = lane; j < NITEM; j += 32) {
            float v = row[j];
            vals[cnt++] = v;
            mx = fmaxf(mx, v);
        }
        #pragma unroll
        for (int o = 16; o; o >>= 1) mx = fmaxf(mx, __shfl_xor_sync(0xffffffffu, mx, o));
        float sum = 0.f;
        for (int i = 0; i < cnt; i++) { vals[i] = __expf(vals[i] - mx); sum += vals[i]; }
        #pragma unroll
        for (int o = 16; o; o >>= 1) sum += __shfl_xor_sync(0xffffffffu, sum, o);
        float inv = 1.f / sum;
        cnt = 0;
        for (int j = lane; j < NITEM; j += 32) row[j] = vals[cnt++] * inv;
    }

    if (t < 144) {
        int m = t >> 3, seg = t & 7;
        float s = 0.f;
        int k0 = seg * 32;
        #pragma unroll 8
        for (int k = k0; k < k0+32; k++) s += sfeat[k] * kps_w[k*18 + m];
        spart[m][seg] = s;
    }
    __syncthreads();
    if (t < 18) {
        float s = kps_b[t];
        #pragma unroll
        for (int seg = 0; seg < 8; seg++) s += spart[t][seg];
        slearn[t] = s;
    }
    __syncthreads();

    if (t < NP*3) {
        int p = t/3, d = t%3;
        float center = sanchor[d];
        float size   = expf(sanchor[3+d]);
        float v = (p < 7) ? c_FIX[p][d] : slearn[(p-7)*3 + d];
        skp[p][d] = center + v * size;
    }
    __syncthreads();

    if (t < NP*NC) {
        int p = t / NC, c = t % NC;
        const float* L = &l2i[c*16];
        float kx = skp[p][0], ky = skp[p][1], kz = skp[p][2];
        float p0 = L[0]*kx + L[1]*ky + L[2]*kz  + L[3];
        float p1 = L[4]*kx + L[5]*ky + L[6]*kz  + L[7];
        float p2 = L[8]*kx + L[9]*ky + L[10]*kz + L[11];
        float z  = fmaxf(p2, 1e-5f);
        suv[(p*NC + c)*2 + 0] = p0 / z / image_wh[c*2 + 0];
        suv[(p*NC + c)*2 + 1] = p1 / z / image_wh[c*2 + 1];
    }
    __syncthreads();

    for (int i = t; i < NITEM; i += 256) {
        int c  = i % NC;
        int lp = i / NC;
        int p  = lp % NP;
        int l  = lp / NP;
        int H = sh[l*2], Wd = sh[l*2+1], st = sh[8+l];
        float fH = (float)H, fW = (float)Wd;
        float u = suv[(p*NC + c)*2 + 0];
        float v = suv[(p*NC + c)*2 + 1];
        float x = u*fW - 0.5f, y = v*fH - 0.5f;
        float x0f = floorf(x), y0f = floorf(y);
        float dx = x - x0f, dy = y - y0f;
        float x1f = x0f + 1.f, y1f = y0f + 1.f;
        bool vx0 = (x0f >= 0.f) && (x0f < fW);
        bool vx1 = (x1f >= 0.f) && (x1f < fW);
        bool vy0 = (y0f >= 0.f) && (y0f < fH);
        bool vy1 = (y1f >= 0.f) && (y1f < fH);
        int x0 = vx0 ? (int)x0f : 0;
        int x1 = vx1 ? (int)x1f : 0;
        int y0 = vy0 ? (int)y0f : 0;
        int y1 = vy1 ? (int)y1f : 0;

        float4 w;
        w.x = (vx0 && vy0) ? (1.f-dx)*(1.f-dy) : 0.f;
        w.y = (vx1 && vy0) ? dx*(1.f-dy)       : 0.f;
        w.z = (vx0 && vy1) ? (1.f-dx)*dy       : 0.f;
        w.w = (vx1 && vy1) ? dx*dy             : 0.f;

        int base = (c*T + st)*ED;
        int4 o;
        o.x = (base + (y0*Wd + x0)*ED) >> 2;
        o.y = (base + (y0*Wd + x1)*ED) >> 2;
        o.z = (base + (y1*Wd + x0)*ED) >> 2;
        o.w = (base + (y1*Wd + x1)*ED) >> 2;

        sValid[i] = ((w.x != 0.f) | (w.y != 0.f) | (w.z != 0.f) | (w.w != 0.f)) ? 1 : 0;
        sWi[i]    = c*52 + l*13 + p;
        sOff[i]   = o;
        sCw[i]    = w;
    }
    __syncthreads();

    if (t < 32) {
        const int CH = (NITEM + 31) / 32;
        int start = t * CH;
        int end = start + CH; if (end > NITEM) end = NITEM;
        int cnt = 0;
        for (int i = start; i < end; i++) cnt += sValid[i];
        int x = cnt;
        #pragma unroll
        for (int o = 1; o < 32; o <<= 1) {
            int y = __shfl_up_sync(0xffffffffu, x, o);
            if (t >= o) x += y;
        }
        int pos = x - cnt;
        for (int i = start; i < end; i++)
            if (sValid[i]) sIdx[pos++] = (short)i;
        if (t == 31) s_nv = x;
    }
    __syncthreads();

    {
        int chunk = t >> 6;
        int ch = t & 63;
        int g = ch >> 3;
        const float4* fb = (const float4*)feature;
        int nv = s_nv;
        ull acc01 = 0ull, acc23 = 0ull;
        for (int ii = chunk; ii < nv; ii += 4) {
            int i = sIdx[ii];
            float aw = sWt[g*WSTR + sWi[i]];
            float4 w = sCw[i];
            int4  o = sOff[i];
            if (w.x != 0.f) {
                float4 f = fb[o.x + ch];
                float wc = w.x * aw; ull wd = pack2(wc, wc);
                ffma2(acc01, wd, pack2(f.x, f.y));
                ffma2(acc23, wd, pack2(f.z, f.w));
            }
            if (w.y != 0.f) {
                float4 f = fb[o.y + ch];
                float wc = w.y * aw; ull wd = pack2(wc, wc);
                ffma2(acc01, wd, pack2(f.x, f.y));
                ffma2(acc23, wd, pack2(f.z, f.w));
            }
            if (w.z != 0.f) {
                float4 f = fb[o.z + ch];
                float wc = w.z * aw; ull wd = pack2(wc, wc);
                ffma2(acc01, wd, pack2(f.x, f.y));
                ffma2(acc23, wd, pack2(f.z, f.w));
            }
            if (w.w != 0.f) {
                float4 f = fb[o.w + ch];
                float wc = w.w * aw; ull wd = pack2(wc, wc);
                ffma2(acc01, wd, pack2(f.x, f.y));
                ffma2(acc23, wd, pack2(f.z, f.w));
            }
        }
        float4 r;
        unpack2(acc01, r.x, r.y);
        unpack2(acc23, r.z, r.w);
        sPart[chunk][ch] = r;
    }
    __syncthreads();
    if (t < 64) {
        float4 p0 = sPart[0][t], p1 = sPart[1][t], p2 = sPart[2][t], p3 = sPart[3][t];
        float4 r;
        r.x = ((p0.x + p1.x) + p2.x) + p3.x;
        r.y = ((p0.y + p1.y) + p2.y) + p3.y;
        r.z = ((p0.z + p1.z) + p2.z) + p3.z;
        r.w = ((p0.w + p1.w) + p2.w) + p3.w;
        *(float4*)&feats_out[a*ED + t*4] = r;
    }
}

// ===================== k5: split-K ffn + heads (ping-pong, dyn smem) ======
#define FM 16
#define NB5 ((NA + FM - 1) / FM)   // 57
#define K5_FLOATS (4096 + 4096 + 4096 + 4096 + 4096)   // sA,sI,sU0x2,sU1x2,sP
#define K5_SMEM (K5_FLOATS*4)      // 80 KB
__global__ void __launch_bounds__(512, 1)
k5_fused(const float* __restrict__ feats,
         const float* __restrict__ Wc,
         const float* __restrict__ bc,
         const float* __restrict__ Wf,
         const float* __restrict__ reg_w,  const float* __restrict__ reg_b,
         const float* __restrict__ cls_w,  const float* __restrict__ cls_b,
         const float* __restrict__ qt_w,   const float* __restrict__ qt_b,
         const float* __restrict__ time_interval,
         const float* __restrict__ instR, float* __restrict__ instW,
         const float* __restrict__ anchR, float* __restrict__ anchW,
         int cls_mode, float* cls_dst,
         int qt_on, float* qt_dst)
{
    extern __shared__ __align__(16) float smem5[];
    float* sA  = smem5;              // 4096: feats ; later reg_w+qt_w
    float* sI  = sA + 4096;          // 4096: inst ; later newinst^T [256][16]
    float* sU0 = sI + 4096;          // 4096: group A weight tiles (x2)
    float* sU1 = sU0 + 4096;         // 4096: group B weight tiles (x2)
    float* sP  = sU1 + 4096;         // 4096: group B partial ; later cls_w

    int t = threadIdx.x;
    int g = t >> 8;
    int tt = t & 255;
    int tRow = tt >> 6;
    int tCol = tt & 63;
    int r0 = blockIdx.x * FM;

    for (int idx = t; idx < FM*256; idx += 512) {
        int r = idx >> 8, c = idx & 255;
        int row = r0 + r;
        sA[idx] = (row < NA) ? feats[row*ED + c] : 0.f;
        sI[idx] = (row < NA) ? instR[row*ED + c] : 0.f;
    }
    __syncthreads();

    const float* Wg = (g == 0) ? Wc : (Wf + ED*ED);
    float* sUg = (g == 0) ? sU0 : sU1;
    const float* sXg = (g == 0) ? sA : sI;
    int lr0 = tt >> 6, lc0 = tt & 63;

    ull acc[4][2];
    #pragma unroll
    for (int i = 0; i < 4; i++) { acc[i][0] = 0ull; acc[i][1] = 0ull; }

    float4 bv0 = *(const float4*)&Wg[(lr0)*ED + lc0*4];
    float4 bv1 = *(const float4*)&Wg[(lr0+4)*ED + lc0*4];

    for (int kt = 0; kt < 32; kt++) {
        float* buf = sUg + (kt & 1) * 2048;
        *(float4*)&buf[lr0*256 + lc0*4]     = bv0;
        *(float4*)&buf[(lr0+4)*256 + lc0*4] = bv1;
        __syncthreads();   // single barrier per stage
        if (kt + 1 < 32) {
            bv0 = *(const float4*)&Wg[((kt+1)*8 + lr0)*ED + lc0*4];
            bv1 = *(const float4*)&Wg[((kt+1)*8 + lr0+4)*ED + lc0*4];
        }
        #pragma unroll
        for (int k = 0; k < 8; k++) {
            ull b0 = *(const ull*)&buf[k*256 + tCol*4];
            ull b1 = *(const ull*)&buf[k*256 + tCol*4 + 2];
            int kk = kt*8 + k;
            #pragma unroll
            for (int i = 0; i < 4; i++) {
                float a = sXg[(tRow*4 + i)*256 + kk];
                ull ad = pack2(a, a);
                ffma2(acc[i][0], ad, b0);
                ffma2(acc[i][1], ad, b1);
            }
        }
        // no trailing sync (ping-pong WAR separation)
    }
    __syncthreads();   // all compute done before sP writes

    // group B deposits partials
    if (g == 1) {
        #pragma unroll
        for (int i = 0; i < 4; i++) {
            float x0, y0, x1, y1;
            unpack2(acc[i][0], x0, y0);
            unpack2(acc[i][1], x1, y1);
            *(float4*)&sP[(tRow*4 + i)*256 + tCol*4] = make_float4(x0, y0, x1, y1);
        }
    }
    __syncthreads();

    // group A merges: newinst = relu(accA + partB + bcomb)
    if (g == 0) {
        float4 bc4 = *(const float4*)&bc[tCol*4];
        #pragma unroll
        for (int i = 0; i < 4; i++) {
            float x0, y0, x1, y1;
            unpack2(acc[i][0], x0, y0);
            unpack2(acc[i][1], x1, y1);
            float4 p = *(const float4*)&sP[(tRow*4 + i)*256 + tCol*4];
            float nv0 = fmaxf(x0 + p.x + bc4.x, 0.f);
            float nv1 = fmaxf(y0 + p.y + bc4.y, 0.f);
            float nv2 = fmaxf(x1 + p.z + bc4.z, 0.f);
            float nv3 = fmaxf(y1 + p.w + bc4.w, 0.f);
            int row = r0 + tRow*4 + i;
            if (row < NA)
                *(float4*)&instW[row*ED + tCol*4] = make_float4(nv0, nv1, nv2, nv3);
            int rr = tRow*4 + i;
            sI[(tCol*4 + 0)*16 + rr] = nv0;
            sI[(tCol*4 + 1)*16 + rr] = nv1;
            sI[(tCol*4 + 2)*16 + rr] = nv2;
            sI[(tCol*4 + 3)*16 + rr] = nv3;
        }
    }
    __syncthreads();

    // stage head weights
    bool do_cls = (cls_mode != 0);
    for (int idx = t; idx < ED*ADIM; idx += 512) sA[idx] = reg_w[idx];
    if (do_cls)
        for (int idx = t; idx < ED*NCLS; idx += 512) sP[idx] = cls_w[idx];
    if (qt_on)
        for (int idx = t; idx < ED; idx += 512) sA[ED*ADIM + idx] = qt_w[idx];
    __syncthreads();

    // heads
    float ti = time_interval[0];
    for (int o = t; o < FM*ADIM; o += 512) {
        int r = o / ADIM, j = o % ADIM;
        int row = r0 + r;
        if (row < NA) {
            float s0 = 0.f, s1 = 0.f, s2 = 0.f, s3 = 0.f;
            for (int k = 0; k < ED; k += 4) {
                s0 += sI[(k+0)*16 + r] * sA[(k+0)*ADIM + j];
                s1 += sI[(k+1)*16 + r] * sA[(k+1)*ADIM + j];
                s2 += sI[(k+2)*16 + r] * sA[(k+2)*ADIM + j];
                s3 += sI[(k+3)*16 + r] * sA[(k+3)*ADIM + j];
            }
            float s = reg_b[j] + ((s0 + s1) + (s2 + s3));
            if (j >= 8) s /= ti;
            anchW[row*ADIM + j] = anchR[row*ADIM + j] + s;
        }
    }
    if (do_cls) {
        float* cdst = (cls_mode == 1) ? g_cls : cls_dst;
        for (int o = t; o < FM*NCLS; o += 512) {
            int r = o / NCLS, j = o % NCLS;
            int row = r0 + r;
            if (row < NA) {
                float s0 = 0.f, s1 = 0.f, s2 = 0.f, s3 = 0.f;
                for (int k = 0; k < ED; k += 4) {
                    s0 += sI[(k+0)*16 + r] * sP[(k+0)*NCLS + j];
                    s1 += sI[(k+1)*16 + r] * sP[(k+1)*NCLS + j];
                    s2 += sI[(k+2)*16 + r] * sP[(k+2)*NCLS + j];
                    s3 += sI[(k+3)*16 + r] * sP[(k+3)*NCLS + j];
                }
                cdst[row*NCLS + j] = cls_b[j] + ((s0 + s1) + (s2 + s3));
            }
        }
    }
    if (qt_on) {
        for (int o = t; o < FM; o += 512) {
            int row = r0 + o;
            if (row < NA) {
                float s0 = 0.f, s1 = 0.f, s2 = 0.f, s3 = 0.f;
                for (int k = 0; k < ED; k += 4) {
                    s0 += sI[(k+0)*16 + o] * sA[ED*ADIM + k+0];
                    s1 += sI[(k+1)*16 + o] * sA[ED*ADIM + k+1];
                    s2 += sI[(k+2)*16 + o] * sA[ED*ADIM + k+2];
                    s3 += sI[(k+3)*16 + o] * sA[ED*ADIM + k+3];
                }
                qt_dst[row] = qt_b[0] + ((s0 + s1) + (s2 + s3));
            }
        }
    }
}

// ===================== rank + gather ===============
__global__ void k_rank()
{
    __shared__ float ssc[NA];
    int t = threadIdx.x;
    if (t < NA) {
        float m = -1e30f;
        #pragma unroll
        for (int j = 0; j < NCLS; j++) m = fmaxf(m, g_cls[t*NCLS + j]);
        ssc[t] = m;
    }
    __syncthreads();
    if (t < NA) {
        float sc = ssc[t];
        int cnt = 0;
        for (int b = 0; b < NA; b++) {
            float sb = ssc[b];
            cnt += (sb > sc) || (sb == sc && b < t);
        }
        if (cnt < NSEL) g_sel[NTEMP + cnt] = t;
    }
}

__global__ void k_gather(const float* __restrict__ temp_inst,
                         const float* __restrict__ temp_anchor,
                         const unsigned char* __restrict__ mask)
{
    int r = blockIdx.x, t = threadIdx.x;
    bool m = mask[0] != 0;
    if (m) {
        if (r < NTEMP) {
            g_instB[r*ED + t] = temp_inst[r*ED + t];
            if (t < ADIM) g_anchorB[r*ADIM + t] = temp_anchor[r*ADIM + t];
        } else {
            int s = g_sel[r];
            g_instB[r*ED + t] = g_instA[s*ED + t];
            if (t < ADIM) g_anchorB[r*ADIM + t] = g_anchorA[s*ADIM + t];
        }
    } else {
        g_instB[r*ED + t] = g_instA[r*ED + t];
        if (t < ADIM) g_anchorB[r*ADIM + t] = g_anchorA[r*ADIM + t];
    }
}

// ===================== finalize ===========================================
__global__ void k_finalize(float* __restrict__ out,
                           const int* __restrict__ track_id,
                           const unsigned char* __restrict__ mask)
{
    int i = blockIdx.x*blockDim.x + threadIdx.x;
    if (i < NA*ED)   out[OFF_INST + i]   = g_instB[i];
    if (i < NA*ADIM) out[OFF_ANCHOR + i] = g_anchorB[i];
    if (i < NA) {
        bool m = mask[0] != 0;
        out[OFF_TRACK + i] = m ? (float)track_id[i] : -1.0f;
    }
}

// ===================== host ===============================================
extern "C" void kernel_launch(void* const* d_in, const int* in_sizes, int n_in,
                              void* d_out, int out_size)
{
    const float* feature      = (const float*)d_in[0];
    const int*   ss           = (const int*)d_in[1];
    const int*   lsi          = (const int*)d_in[2];
    const float* inst_in      = (const float*)d_in[3];
    const float* anchor_in    = (const float*)d_in[4];
    const float* ti           = (const float*)d_in[5];
    const float* temp_inst    = (const float*)d_in[6];
    const float* temp_anchor  = (const float*)d_in[7];
    const unsigned char* mask = (const unsigned char*)d_in[8];
    const int*   track_id     = (const int*)d_in[9];
    const float* image_wh     = (const float*)d_in[10];
    const float* l2i          = (const float*)d_in[11];
    const float* anchor_w     = (const float*)d_in[12];
    const float* anchor_b     = (const float*)d_in[13];
    const float* kps_w        = (const float*)d_in[14];
    const float* kps_b        = (const float*)d_in[15];
    const float* wfc_w        = (const float*)d_in[16];
    const float* wfc_b        = (const float*)d_in[17];
    const float* outp_w       = (const float*)d_in[18];
    const float* outp_b       = (const float*)d_in[19];
    const float* ffn_w        = (const float*)d_in[20];
    const float* ffn_b        = (const float*)d_in[21];
    const float* reg_w        = (const float*)d_in[22];
    const float* reg_b        = (const float*)d_in[23];
    const float* cls_w        = (const float*)d_in[24];
    const float* cls_b        = (const float*)d_in[25];
    const float* qt_w         = (const float*)d_in[26];
    const float* qt_b         = (const float*)d_in[27];

    int T = in_sizes[0] / (NC*ED);
    float* out = (float*)d_out;

    static float *p_instA = nullptr, *p_instB = nullptr, *p_anchorA = nullptr,
                 *p_anchorB = nullptr, *p_Wcomb = nullptr, *p_bcomb = nullptr,
                 *p_AWm = nullptr;
    static bool init_done = false;
    if (!init_done) {
        cudaGetSymbolAddress((void**)&p_instA,   g_instA);
        cudaGetSymbolAddress((void**)&p_instB,   g_instB);
        cudaGetSymbolAddress((void**)&p_anchorA, g_anchorA);
        cudaGetSymbolAddress((void**)&p_anchorB, g_anchorB);
        cudaGetSymbolAddress((void**)&p_Wcomb,   g_Wcomb);
        cudaGetSymbolAddress((void**)&p_bcomb,   g_bcomb);
        cudaGetSymbolAddress((void**)&p_AWm,     g_AWm);
        cudaFuncSetAttribute(k5_fused, cudaFuncAttributeMaxDynamicSharedMemorySize, K5_SMEM);
        init_done = true;
    }

    kP1a<<<dim3(4,4,6), 256>>>(outp_w, ffn_w);
    kP1b<<<6, 256>>>(outp_b, ffn_w, ffn_b);
    kP2<<<dim3(26,6), 256>>>(anchor_w, anchor_b, wfc_w);

    for (int i = 0; i < NDEC; i++) {
        const float* instR = (i == 0) ? inst_in   : p_instB;
        float*       instW = (i == 0) ? p_instA   : p_instB;
        const float* anchR = (i == 0) ? anchor_in : p_anchorB;
        float*       anchW = (i == 0) ? p_anchorA : p_anchorB;

        dim3 g2(WTOT/BN, (NA + BM - 1)/BM);
        k2_wfc_gemm<<<g2, 256>>>(instR, anchR,
                                 wfc_w + (size_t)i*ED*WTOT,
                                 wfc_b + (size_t)i*WTOT,
                                 p_AWm + (size_t)i*12*WTOT);

        float* feats = out + OFF_TMP + (size_t)i*NA*ED;
        k4_daf<<<NA, 256>>>(feature, ss, lsi, T, feats, instR, anchR,
                            kps_w + (size_t)i*ED*NLEARN*3,
                            kps_b + (size_t)i*NLEARN*3,
                            l2i, image_wh);

        int cls_mode = (i == 0) ? 1 : ((i == NDEC-1) ? 2 : 0);
        int qt_on    = (i == NDEC-1) ? 1 : 0;
        k5_fused<<<NB5, 512, K5_SMEM>>>(feats,
                    p_Wcomb + (size_t)i*ED*ED,
                    p_bcomb + (size_t)i*ED,
                    ffn_w  + (size_t)i*2*ED*ED,
                    reg_w  + (size_t)i*ED*ADIM,  reg_b  + (size_t)i*ADIM,
                    cls_w  + (size_t)i*ED*NCLS,  cls_b  + (size_t)i*NCLS,
                    qt_w   + (size_t)i*ED,       qt_b   + (size_t)i,
                    ti, instR, instW, anchR, anchW,
                    cls_mode, out + OFF_CLS, qt_on, out + OFF_QT);

        if (i == 0) {
            k_rank<<<1, 1024>>>();
            k_gather<<<NA, 256>>>(temp_inst, temp_anchor, mask);
        }
    }

    k_finalize<<<(NA*ED + 255)/256, 256>>>(out, track_id, mask);
}

// round 15
// speedup vs baseline: 1.0250x; 1.0250x over previous
#include <cuda_runtime.h>
#include <cuda_bf16.h>
#include <math.h>

#define NA    900
#define NTEMP 600
#define ED    256
#define NC    6
#define NL    4
#define NP    13
#define NG    8
#define NLEARN 6
#define NDEC  6
#define ADIM  11
#define NCLS  10
#define WTOT  (NC*NL*NP*NG)   // 2496
#define NSEL  (NA-NTEMP)      // 300
#define NITEM (NL*NP*NC)      // 312
#define WSTR  313             // transposed softmax row stride

typedef unsigned long long ull;

// -------- output layout (flattened tuple, float32) --------
#define OFF_INST   0
#define OFF_ANCHOR (NA*ED)
#define OFF_CLS    (OFF_ANCHOR + NA*ADIM)
#define OFF_QT     (OFF_CLS + NA*NCLS)
#define OFF_TRACK  (OFF_QT + NA)
#define OFF_TMP    (OFF_TRACK + NA)

// -------- scratch --------
__device__ __align__(16) float g_instA[NA*ED];
__device__ __align__(16) float g_instB[NA*ED];
__device__ __align__(16) float g_anchorA[NA*ADIM];
__device__ __align__(16) float g_anchorB[NA*ADIM];
__device__ __align__(16) float g_W[NA*WTOT];
__device__ __align__(16) float g_cls[NA*NCLS];
__device__ __align__(16) float g_Wcomb[NDEC*ED*ED];
__device__ __align__(16) float g_bcomb[NDEC*ED];
__device__ __align__(16) float g_AWm[NDEC*12*WTOT];
__device__ int g_sel[NA];

__constant__ float c_FIX[7][3] = {
    {0.f,0.f,0.f},{0.5f,0.f,0.f},{-0.5f,0.f,0.f},
    {0.f,0.5f,0.f},{0.f,-0.5f,0.f},{0.f,0.f,0.5f},{0.f,0.f,-0.5f}};

// ---- f32x2 helpers ----
__device__ __forceinline__ ull pack2(float x, float y) {
    ull r;
    asm("mov.b64 %0, {%1, %2};" : "=l"(r) : "f"(x), "f"(y));
    return r;
}
__device__ __forceinline__ void unpack2(ull v, float& x, float& y) {
    asm("mov.b64 {%0, %1}, %2;" : "=f"(x), "=f"(y) : "l"(v));
}
__device__ __forceinline__ void ffma2(ull& acc, ull a, ull b) {
    asm("fma.rn.f32x2 %0, %1, %2, %0;" : "+l"(acc) : "l"(a), "l"(b));
}

// ===================== P1a: Wcomb = Wo @ Wf1 (per iter) ===================
__global__ void kP1a(const float* __restrict__ outp_w,
                     const float* __restrict__ ffn_w)
{
    int i = blockIdx.z;
    const float* A = outp_w + (size_t)i*ED*ED;
    const float* B = ffn_w + (size_t)i*2*ED*ED;
    float* C = g_Wcomb + (size_t)i*ED*ED;

    __shared__ __align__(16) float As[64][16];
    __shared__ __align__(16) float Bs[16][64];

    int tid = threadIdx.x;
    int tRow = tid >> 4, tCol = tid & 15;
    int m0 = blockIdx.y * 64, n0 = blockIdx.x * 64;
    int aRow = tid >> 2, aK4 = (tid & 3) * 4;
    int bRow = tid >> 4, bCol = (tid & 15) * 4;

    ull acc[4][2];
    #pragma unroll
    for (int r = 0; r < 4; r++) { acc[r][0] = 0ull; acc[r][1] = 0ull; }

    for (int k0 = 0; k0 < ED; k0 += 16) {
        *(float4*)&As[aRow][aK4] = *(const float4*)&A[(m0+aRow)*ED + k0 + aK4];
        *(float4*)&Bs[bRow][bCol] = *(const float4*)&B[(k0+bRow)*ED + n0 + bCol];
        __syncthreads();
        #pragma unroll
        for (int k = 0; k < 16; k++) {
            ull b0 = *(const ull*)&Bs[k][tCol*4 + 0];
            ull b1 = *(const ull*)&Bs[k][tCol*4 + 2];
            #pragma unroll
            for (int r = 0; r < 4; r++) {
                float a = As[tRow*4 + r][k];
                ull ad = pack2(a, a);
                ffma2(acc[r][0], ad, b0);
                ffma2(acc[r][1], ad, b1);
            }
        }
        __syncthreads();
    }
    #pragma unroll
    for (int r = 0; r < 4; r++) {
        float x0, y0, x1, y1;
        unpack2(acc[r][0], x0, y0);
        unpack2(acc[r][1], x1, y1);
        *(float4*)&C[(m0+tRow*4+r)*ED + n0 + tCol*4] = make_float4(x0, y0, x1, y1);
    }
}

// ===================== P1b: bcomb = bo@Wf1 + bf ===========================
__global__ void kP1b(const float* __restrict__ outp_b,
                     const float* __restrict__ ffn_w,
                     const float* __restrict__ ffn_b)
{
    int i = blockIdx.x;
    const float* bo = outp_b + (size_t)i*ED;
    const float* Wf = ffn_w + (size_t)i*2*ED*ED;
    const float* bf = ffn_b + (size_t)i*ED;
    int t = threadIdx.x;
    __shared__ float sbo[ED];
    sbo[t] = bo[t];
    __syncthreads();
    float s0 = 0.f, s1 = 0.f, s2 = 0.f, s3 = 0.f;
    for (int n = 0; n < ED; n += 4) {
        s0 += sbo[n+0] * Wf[(n+0)*ED + t];
        s1 += sbo[n+1] * Wf[(n+1)*ED + t];
        s2 += sbo[n+2] * Wf[(n+2)*ED + t];
        s3 += sbo[n+3] * Wf[(n+3)*ED + t];
    }
    g_bcomb[i*ED + t] = bf[t] + ((s0 + s1) + (s2 + s3));
}

// ===================== P2: AWm = [anchor_w;anchor_b] @ wfc ================
__global__ void kP2(const float* __restrict__ anchor_w,
                    const float* __restrict__ anchor_b,
                    const float* __restrict__ wfc_w)
{
    int i = blockIdx.y;
    int n0 = blockIdx.x * 96;
    const float* Wm = wfc_w + (size_t)i*ED*WTOT;
    float* dst = g_AWm + (size_t)i*12*WTOT;
    int t = threadIdx.x;

    __shared__ float sAw[12*ED];
    __shared__ float sT[32*96];

    for (int idx = t; idx < 11*ED; idx += 256) sAw[idx] = anchor_w[idx];
    for (int idx = t; idx < ED; idx += 256)    sAw[11*ED + idx] = anchor_b[idx];
    __syncthreads();

    float acc[5] = {0.f,0.f,0.f,0.f,0.f};
    for (int k0 = 0; k0 < ED; k0 += 32) {
        for (int idx = t; idx < 32*96; idx += 256) {
            int kk = idx / 96, nc = idx % 96;
            sT[idx] = Wm[(size_t)(k0+kk)*WTOT + n0 + nc];
        }
        __syncthreads();
        int slot = 0;
        for (int o = t; o < 12*96; o += 256, slot++) {
            int j = o / 96, nc = o % 96;
            float s = acc[slot];
            #pragma unroll 8
            for (int kk = 0; kk < 32; kk++)
                s += sAw[j*ED + k0 + kk] * sT[kk*96 + nc];
            acc[slot] = s;
        }
        __syncthreads();
    }
    int slot = 0;
    for (int o = t; o < 12*96; o += 256, slot++) {
        int j = o / 96, nc = o % 96;
        dst[(size_t)j*WTOT + n0 + nc] = acc[slot];
    }
}

// ===================== k2: wfc GEMM + rank-12 fold (R12 single-buffer) ====
#define BM 64
#define BN 96
#define BK 16
__global__ void k2_wfc_gemm(const float* __restrict__ instR,
                            const float* __restrict__ anchR,
                            const float* __restrict__ Wm,
                            const float* __restrict__ bias,
                            const float* __restrict__ AWm)
{
    __shared__ __align__(16) float As[BM][BK];
    __shared__ __align__(16) float Bs[BK][BN];
    __shared__ float sAnchT[BM][12];
    __shared__ __align__(8) float sAW[12][BN];

    int tid  = threadIdx.x;
    int tRow = tid >> 4, tCol = tid & 15;
    int m0 = blockIdx.y * BM, n0 = blockIdx.x * BN;

    for (int idx = tid; idx < BM*ADIM; idx += 256) {
        int r = idx / ADIM, j = idx % ADIM;
        int row = m0 + r;
        sAnchT[r][j] = (row < NA) ? anchR[row*ADIM + j] : 0.f;
    }
    for (int idx = tid; idx < 12*BN; idx += 256) {
        int j = idx / BN, nc = idx % BN;
        sAW[j][nc] = AWm[(size_t)j*WTOT + n0 + nc];
    }

    ull acc[4][3];
    #pragma unroll
    for (int i = 0; i < 4; i++)
        #pragma unroll
        for (int j = 0; j < 3; j++) acc[i][j] = 0ull;

    int aRow = tid >> 2;
    int aK4  = (tid & 3) * 4;
    int gm   = m0 + aRow;
    bool mok = (gm < NA);

    int bR[3], bC[3];
    #pragma unroll
    for (int it = 0; it < 3; it++) {
        int lin = tid + it*256;
        bR[it] = lin / 48;
        bC[it] = (lin % 48) * 2;
    }

    float4 avr = mok ? *(const float4*)&instR[gm*ED + aK4] : make_float4(0.f,0.f,0.f,0.f);
    float2 bvr[3];
    #pragma unroll
    for (int it = 0; it < 3; it++)
        bvr[it] = *(const float2*)&Wm[(size_t)bR[it]*WTOT + n0 + bC[it]];

    for (int k0 = 0; k0 < ED; k0 += BK) {
        *(float4*)&As[aRow][aK4] = avr;
        #pragma unroll
        for (int it = 0; it < 3; it++)
            *(float2*)&Bs[bR[it]][bC[it]] = bvr[it];
        __syncthreads();

        int k0n = k0 + BK;
        if (k0n < ED) {
            if (mok) avr = *(const float4*)&instR[gm*ED + k0n + aK4];
            #pragma unroll
            for (int it = 0; it < 3; it++)
                bvr[it] = *(const float2*)&Wm[(size_t)(k0n + bR[it])*WTOT + n0 + bC[it]];
        }

        #pragma unroll
        for (int k = 0; k < BK; k++) {
            ull b0 = *(const ull*)&Bs[k][tCol*6 + 0];
            ull b1 = *(const ull*)&Bs[k][tCol*6 + 2];
            ull b2 = *(const ull*)&Bs[k][tCol*6 + 4];
            #pragma unroll
            for (int i = 0; i < 4; i++) {
                float a = As[tRow*4 + i][k];
                ull ad = pack2(a, a);
                ffma2(acc[i][0], ad, b0);
                ffma2(acc[i][1], ad, b1);
                ffma2(acc[i][2], ad, b2);
            }
        }
        __syncthreads();
    }

    float2 bb[3];
    #pragma unroll
    for (int j = 0; j < 3; j++)
        bb[j] = *(const float2*)&bias[n0 + tCol*6 + 2*j];

    #pragma unroll
    for (int i = 0; i < 4; i++) {
        int lr = tRow*4 + i;
        int r = m0 + lr;
        if (r >= NA) continue;
        ull corr[3];
        #pragma unroll
        for (int j = 0; j < 3; j++)
            corr[j] = *(const ull*)&sAW[11][tCol*6 + 2*j];
        #pragma unroll
        for (int j = 0; j < ADIM; j++) {
            float a = sAnchT[lr][j];
            ull ad = pack2(a, a);
            ffma2(corr[0], ad, *(const ull*)&sAW[j][tCol*6 + 0]);
            ffma2(corr[1], ad, *(const ull*)&sAW[j][tCol*6 + 2]);
            ffma2(corr[2], ad, *(const ull*)&sAW[j][tCol*6 + 4]);
        }
        #pragma unroll
        for (int j = 0; j < 3; j++) {
            float x, y, cx, cy;
            unpack2(acc[i][j], x, y);
            unpack2(corr[j], cx, cy);
            float2 v = make_float2(x + cx + bb[j].x, y + cy + bb[j].y);
            *(float2*)&g_W[(size_t)r*WTOT + n0 + tCol*6 + 2*j] = v;
        }
    }
}

// ===================== k4: kps/proj + softmax + chunked aggregation =======
__global__ void k4_daf(const float* __restrict__ feature,
                       const int* __restrict__ ss,
                       const int* __restrict__ lsi,
                       int T,
                       float* __restrict__ feats_out,
                       const float* __restrict__ instR,
                       const float* __restrict__ anchR,
                       const float* __restrict__ kps_w,
                       const float* __restrict__ kps_b,
                       const float* __restrict__ l2i,
                       const float* __restrict__ image_wh)
{
    int a = blockIdx.x, t = threadIdx.x, g8 = t >> 5, lane = t & 31;

    __shared__ float sWt[NG*WSTR];
    __shared__ float sfeat[ED];
    __shared__ float sanchor[ADIM];
    __shared__ float spart[18][8];
    __shared__ float slearn[18];
    __shared__ float skp[NP][3];
    __shared__ float suv[NP*NC*2];
    __shared__ int   sh[12];
    __shared__ int   sValid[NITEM];
    __shared__ int   sWi[NITEM];
    __shared__ int4  sOff[NITEM];
    __shared__ float4 sCw[NITEM];
    __shared__ short sIdx[NITEM];
    __shared__ int   s_nv;
    __shared__ __align__(16) float4 sPart[4][64];

    for (int idx = t; idx < WTOT; idx += 256) {
        float v = g_W[(size_t)a*WTOT + idx];
        sWt[(idx & 7)*WSTR + (idx >> 3)] = v;
    }
    sfeat[t] = instR[a*ED + t];
    if (t < ADIM) sanchor[t] = anchR[a*ADIM + t];
    if (t < 8) sh[t]   = ss[t];
    if (t < 4) sh[8+t] = lsi[t];
    __syncthreads();

    {
        float* row = &sWt[g8*WSTR];
        float vals[10];
        float mx = -1e30f;
        int cnt = 0;
        for (int j = lane; j < NITEM; j += 32) {
            float v = row[j];
            vals[cnt++] = v;
            mx = fmaxf(mx, v);
        }
        #pragma unroll
        for (int o = 16; o; o >>= 1) mx = fmaxf(mx, __shfl_xor_sync(0xffffffffu, mx, o));
        float sum = 0.f;
        for (int i = 0; i < cnt; i++) { vals[i] = __expf(vals[i] - mx); sum += vals[i]; }
        #pragma unroll
        for (int o = 16; o; o >>= 1) sum += __shfl_xor_sync(0xffffffffu, sum, o);
        float inv = 1.f / sum;
        cnt = 0;
        for (int j = lane; j < NITEM; j += 32) row[j] = vals[cnt++] * inv;
    }

    if (t < 144) {
        int m = t >> 3, seg = t & 7;
        float s = 0.f;
        int k0 = seg * 32;
        #pragma unroll 8
        for (int k = k0; k < k0+32; k++) s += sfeat[k] * kps_w[k*18 + m];
        spart[m][seg] = s;
    }
    __syncthreads();
    if (t < 18) {
        float s = kps_b[t];
        #pragma unroll
        for (int seg = 0; seg < 8; seg++) s += spart[t][seg];
        slearn[t] = s;
    }
    __syncthreads();

    if (t < NP*3) {
        int p = t/3, d = t%3;
        float center = sanchor[d];
        float size   = expf(sanchor[3+d]);
        float v = (p < 7) ? c_FIX[p][d] : slearn[(p-7)*3 + d];
        skp[p][d] = center + v * size;
    }
    __syncthreads();

    if (t < NP*NC) {
        int p = t / NC, c = t % NC;
        const float* L = &l2i[c*16];
        float kx = skp[p][0], ky = skp[p][1], kz = skp[p][2];
        float p0 = L[0]*kx + L[1]*ky + L[2]*kz  + L[3];
        float p1 = L[4]*kx + L[5]*ky + L[6]*kz  + L[7];
        float p2 = L[8]*kx + L[9]*ky + L[10]*kz + L[11];
        float z  = fmaxf(p2, 1e-5f);
        suv[(p*NC + c)*2 + 0] = p0 / z / image_wh[c*2 + 0];
        suv[(p*NC + c)*2 + 1] = p1 / z / image_wh[c*2 + 1];
    }
    __syncthreads();

    for (int i = t; i < NITEM; i += 256) {
        int c  = i % NC;
        int lp = i / NC;
        int p  = lp % NP;
        int l  = lp / NP;
        int H = sh[l*2], Wd = sh[l*2+1], st = sh[8+l];
        float fH = (float)H, fW = (float)Wd;
        float u = suv[(p*NC + c)*2 + 0];
        float v = suv[(p*NC + c)*2 + 1];
        float x = u*fW - 0.5f, y = v*fH - 0.5f;
        float x0f = floorf(x), y0f = floorf(y);
        float dx = x - x0f, dy = y - y0f;
        float x1f = x0f + 1.f, y1f = y0f + 1.f;
        bool vx0 = (x0f >= 0.f) && (x0f < fW);
        bool vx1 = (x1f >= 0.f) && (x1f < fW);
        bool vy0 = (y0f >= 0.f) && (y0f < fH);
        bool vy1 = (y1f >= 0.f) && (y1f < fH);
        int x0 = vx0 ? (int)x0f : 0;
        int x1 = vx1 ? (int)x1f : 0;
        int y0 = vy0 ? (int)y0f : 0;
        int y1 = vy1 ? (int)y1f : 0;

        float4 w;
        w.x = (vx0 && vy0) ? (1.f-dx)*(1.f-dy) : 0.f;
        w.y = (vx1 && vy0) ? dx*(1.f-dy)       : 0.f;
        w.z = (vx0 && vy1) ? (1.f-dx)*dy       : 0.f;
        w.w = (vx1 && vy1) ? dx*dy             : 0.f;

        int base = (c*T + st)*ED;
        int4 o;
        o.x = (base + (y0*Wd + x0)*ED) >> 2;
        o.y = (base + (y0*Wd + x1)*ED) >> 2;
        o.z = (base + (y1*Wd + x0)*ED) >> 2;
        o.w = (base + (y1*Wd + x1)*ED) >> 2;

        sValid[i] = ((w.x != 0.f) | (w.y != 0.f) | (w.z != 0.f) | (w.w != 0.f)) ? 1 : 0;
        sWi[i]    = c*52 + l*13 + p;
        sOff[i]   = o;
        sCw[i]    = w;
    }
    __syncthreads();

    if (t < 32) {
        const int CH = (NITEM + 31) / 32;
        int start = t * CH;
        int end = start + CH; if (end > NITEM) end = NITEM;
        int cnt = 0;
        for (int i = start; i < end; i++) cnt += sValid[i];
        int x = cnt;
        #pragma unroll
        for (int o = 1; o < 32; o <<= 1) {
            int y = __shfl_up_sync(0xffffffffu, x, o);
            if (t >= o) x += y;
        }
        int pos = x - cnt;
        for (int i = start; i < end; i++)
            if (sValid[i]) sIdx[pos++] = (short)i;
        if (t == 31) s_nv = x;
    }
    __syncthreads();

    {
        int chunk = t >> 6;
        int ch = t & 63;
        int g = ch >> 3;
        const float4* fb = (const float4*)feature;
        int nv = s_nv;
        ull acc01 = 0ull, acc23 = 0ull;
        for (int ii = chunk; ii < nv; ii += 4) {
            int i = sIdx[ii];
            float aw = sWt[g*WSTR + sWi[i]];
            float4 w = sCw[i];
            int4  o = sOff[i];
            if (w.x != 0.f) {
                float4 f = fb[o.x + ch];
                float wc = w.x * aw; ull wd = pack2(wc, wc);
                ffma2(acc01, wd, pack2(f.x, f.y));
                ffma2(acc23, wd, pack2(f.z, f.w));
            }
            if (w.y != 0.f) {
                float4 f = fb[o.y + ch];
                float wc = w.y * aw; ull wd = pack2(wc, wc);
                ffma2(acc01, wd, pack2(f.x, f.y));
                ffma2(acc23, wd, pack2(f.z, f.w));
            }
            if (w.z != 0.f) {
                float4 f = fb[o.z + ch];
                float wc = w.z * aw; ull wd = pack2(wc, wc);
                ffma2(acc01, wd, pack2(f.x, f.y));
                ffma2(acc23, wd, pack2(f.z, f.w));
            }
            if (w.w != 0.f) {
                float4 f = fb[o.w + ch];
                float wc = w.w * aw; ull wd = pack2(wc, wc);
                ffma2(acc01, wd, pack2(f.x, f.y));
                ffma2(acc23, wd, pack2(f.z, f.w));
            }
        }
        float4 r;
        unpack2(acc01, r.x, r.y);
        unpack2(acc23, r.z, r.w);
        sPart[chunk][ch] = r;
    }
    __syncthreads();
    if (t < 64) {
        float4 p0 = sPart[0][t], p1 = sPart[1][t], p2 = sPart[2][t], p3 = sPart[3][t];
        float4 r;
        r.x = ((p0.x + p1.x) + p2.x) + p3.x;
        r.y = ((p0.y + p1.y) + p2.y) + p3.y;
        r.z = ((p0.z + p1.z) + p2.z) + p3.z;
        r.w = ((p0.w + p1.w) + p2.w) + p3.w;
        *(float4*)&feats_out[a*ED + t*4] = r;
    }
}

// ===================== k5: split-K ffn + heads (ping-pong, dyn smem) ======
#define FM 16
#define NB5 ((NA + FM - 1) / FM)   // 57
#define K5_FLOATS (4096 + 4096 + 4096 + 4096 + 4096)
#define K5_SMEM (K5_FLOATS*4)      // 80 KB
__global__ void __launch_bounds__(512, 1)
k5_fused(const float* __restrict__ feats,
         const float* __restrict__ Wc,
         const float* __restrict__ bc,
         const float* __restrict__ Wf,
         const float* __restrict__ reg_w,  const float* __restrict__ reg_b,
         const float* __restrict__ cls_w,  const float* __restrict__ cls_b,
         const float* __restrict__ qt_w,   const float* __restrict__ qt_b,
         const float* __restrict__ time_interval,
         const float* __restrict__ instR, float* __restrict__ instW,
         const float* __restrict__ anchR, float* __restrict__ anchW,
         int cls_mode, float* cls_dst,
         int qt_on, float* qt_dst)
{
    extern __shared__ __align__(16) float smem5[];
    float* sA  = smem5;
    float* sI  = sA + 4096;
    float* sU0 = sI + 4096;
    float* sU1 = sU0 + 4096;
    float* sP  = sU1 + 4096;

    int t = threadIdx.x;
    int g = t >> 8;
    int tt = t & 255;
    int tRow = tt >> 6;
    int tCol = tt & 63;
    int r0 = blockIdx.x * FM;

    for (int idx = t; idx < FM*256; idx += 512) {
        int r = idx >> 8, c = idx & 255;
        int row = r0 + r;
        sA[idx] = (row < NA) ? feats[row*ED + c] : 0.f;
        sI[idx] = (row < NA) ? instR[row*ED + c] : 0.f;
    }
    __syncthreads();

    const float* Wg = (g == 0) ? Wc : (Wf + ED*ED);
    float* sUg = (g == 0) ? sU0 : sU1;
    const float* sXg = (g == 0) ? sA : sI;
    int lr0 = tt >> 6, lc0 = tt & 63;

    ull acc[4][2];
    #pragma unroll
    for (int i = 0; i < 4; i++) { acc[i][0] = 0ull; acc[i][1] = 0ull; }

    float4 bv0 = *(const float4*)&Wg[(lr0)*ED + lc0*4];
    float4 bv1 = *(const float4*)&Wg[(lr0+4)*ED + lc0*4];

    for (int kt = 0; kt < 32; kt++) {
        float* buf = sUg + (kt & 1) * 2048;
        *(float4*)&buf[lr0*256 + lc0*4]     = bv0;
        *(float4*)&buf[(lr0+4)*256 + lc0*4] = bv1;
        __syncthreads();
        if (kt + 1 < 32) {
            bv0 = *(const float4*)&Wg[((kt+1)*8 + lr0)*ED + lc0*4];
            bv1 = *(const float4*)&Wg[((kt+1)*8 + lr0+4)*ED + lc0*4];
        }
        #pragma unroll
        for (int k = 0; k < 8; k++) {
            ull b0 = *(const ull*)&buf[k*256 + tCol*4];
            ull b1 = *(const ull*)&buf[k*256 + tCol*4 + 2];
            int kk = kt*8 + k;
            #pragma unroll
            for (int i = 0; i < 4; i++) {
                float a = sXg[(tRow*4 + i)*256 + kk];
                ull ad = pack2(a, a);
                ffma2(acc[i][0], ad, b0);
                ffma2(acc[i][1], ad, b1);
            }
        }
    }
    __syncthreads();

    if (g == 1) {
        #pragma unroll
        for (int i = 0; i < 4; i++) {
            float x0, y0, x1, y1;
            unpack2(acc[i][0], x0, y0);
            unpack2(acc[i][1], x1, y1);
            *(float4*)&sP[(tRow*4 + i)*256 + tCol*4] = make_float4(x0, y0, x1, y1);
        }
    }
    __syncthreads();

    if (g == 0) {
        float4 bc4 = *(const float4*)&bc[tCol*4];
        #pragma unroll
        for (int i = 0; i < 4; i++) {
            float x0, y0, x1, y1;
            unpack2(acc[i][0], x0, y0);
            unpack2(acc[i][1], x1, y1);
            float4 p = *(const float4*)&sP[(tRow*4 + i)*256 + tCol*4];
            float nv0 = fmaxf(x0 + p.x + bc4.x, 0.f);
            float nv1 = fmaxf(y0 + p.y + bc4.y, 0.f);
            float nv2 = fmaxf(x1 + p.z + bc4.z, 0.f);
            float nv3 = fmaxf(y1 + p.w + bc4.w, 0.f);
            int row = r0 + tRow*4 + i;
            if (row < NA)
                *(float4*)&instW[row*ED + tCol*4] = make_float4(nv0, nv1, nv2, nv3);
            int rr = tRow*4 + i;
            sI[(tCol*4 + 0)*16 + rr] = nv0;
            sI[(tCol*4 + 1)*16 + rr] = nv1;
            sI[(tCol*4 + 2)*16 + rr] = nv2;
            sI[(tCol*4 + 3)*16 + rr] = nv3;
        }
    }
    __syncthreads();

    bool do_cls = (cls_mode != 0);
    for (int idx = t; idx < ED*ADIM; idx += 512) sA[idx] = reg_w[idx];
    if (do_cls)
        for (int idx = t; idx < ED*NCLS; idx += 512) sP[idx] = cls_w[idx];
    if (qt_on)
        for (int idx = t; idx < ED; idx += 512) sA[ED*ADIM + idx] = qt_w[idx];
    __syncthreads();

    float ti = time_interval[0];
    for (int o = t; o < FM*ADIM; o += 512) {
        int r = o / ADIM, j = o % ADIM;
        int row = r0 + r;
        if (row < NA) {
            float s0 = 0.f, s1 = 0.f, s2 = 0.f, s3 = 0.f;
            for (int k = 0; k < ED; k += 4) {
                s0 += sI[(k+0)*16 + r] * sA[(k+0)*ADIM + j];
                s1 += sI[(k+1)*16 + r] * sA[(k+1)*ADIM + j];
                s2 += sI[(k+2)*16 + r] * sA[(k+2)*ADIM + j];
                s3 += sI[(k+3)*16 + r] * sA[(k+3)*ADIM + j];
            }
            float s = reg_b[j] + ((s0 + s1) + (s2 + s3));
            if (j >= 8) s /= ti;
            anchW[row*ADIM + j] = anchR[row*ADIM + j] + s;
        }
    }
    if (do_cls) {
        float* cdst = (cls_mode == 1) ? g_cls : cls_dst;
        for (int o = t; o < FM*NCLS; o += 512) {
            int r = o / NCLS, j = o % NCLS;
            int row = r0 + r;
            if (row < NA) {
                float s0 = 0.f, s1 = 0.f, s2 = 0.f, s3 = 0.f;
                for (int k = 0; k < ED; k += 4) {
                    s0 += sI[(k+0)*16 + r] * sP[(k+0)*NCLS + j];
                    s1 += sI[(k+1)*16 + r] * sP[(k+1)*NCLS + j];
                    s2 += sI[(k+2)*16 + r] * sP[(k+2)*NCLS + j];
                    s3 += sI[(k+3)*16 + r] * sP[(k+3)*NCLS + j];
                }
                cdst[row*NCLS + j] = cls_b[j] + ((s0 + s1) + (s2 + s3));
            }
        }
    }
    if (qt_on) {
        for (int o = t; o < FM; o += 512) {
            int row = r0 + o;
            if (row < NA) {
                float s0 = 0.f, s1 = 0.f, s2 = 0.f, s3 = 0.f;
                for (int k = 0; k < ED; k += 4) {
                    s0 += sI[(k+0)*16 + o] * sA[ED*ADIM + k+0];
                    s1 += sI[(k+1)*16 + o] * sA[ED*ADIM + k+1];
                    s2 += sI[(k+2)*16 + o] * sA[ED*ADIM + k+2];
                    s3 += sI[(k+3)*16 + o] * sA[ED*ADIM + k+3];
                }
                qt_dst[row] = qt_b[0] + ((s0 + s1) + (s2 + s3));
            }
        }
    }
}

// ===================== rank + gather ===============
__global__ void k_rank()
{
    __shared__ float ssc[NA];
    int t = threadIdx.x;
    if (t < NA) {
        float m = -1e30f;
        #pragma unroll
        for (int j = 0; j < NCLS; j++) m = fmaxf(m, g_cls[t*NCLS + j]);
        ssc[t] = m;
    }
    __syncthreads();
    if (t < NA) {
        float sc = ssc[t];
        int cnt = 0;
        for (int b = 0; b < NA; b++) {
            float sb = ssc[b];
            cnt += (sb > sc) || (sb == sc && b < t);
        }
        if (cnt < NSEL) g_sel[NTEMP + cnt] = t;
    }
}

__global__ void k_gather(const float* __restrict__ temp_inst,
                         const float* __restrict__ temp_anchor,
                         const unsigned char* __restrict__ mask)
{
    int r = blockIdx.x, t = threadIdx.x;
    bool m = mask[0] != 0;
    if (m) {
        if (r < NTEMP) {
            g_instB[r*ED + t] = temp_inst[r*ED + t];
            if (t < ADIM) g_anchorB[r*ADIM + t] = temp_anchor[r*ADIM + t];
        } else {
            int s = g_sel[r];
            g_instB[r*ED + t] = g_instA[s*ED + t];
            if (t < ADIM) g_anchorB[r*ADIM + t] = g_anchorA[s*ADIM + t];
        }
    } else {
        g_instB[r*ED + t] = g_instA[r*ED + t];
        if (t < ADIM) g_anchorB[r*ADIM + t] = g_anchorA[r*ADIM + t];
    }
}

// ===================== finalize ===========================================
__global__ void k_finalize(float* __restrict__ out,
                           const int* __restrict__ track_id,
                           const unsigned char* __restrict__ mask)
{
    int i = blockIdx.x*blockDim.x + threadIdx.x;
    if (i < NA*ED)   out[OFF_INST + i]   = g_instB[i];
    if (i < NA*ADIM) out[OFF_ANCHOR + i] = g_anchorB[i];
    if (i < NA) {
        bool m = mask[0] != 0;
        out[OFF_TRACK + i] = m ? (float)track_id[i] : -1.0f;
    }
}

// ===================== host ===============================================
extern "C" void kernel_launch(void* const* d_in, const int* in_sizes, int n_in,
                              void* d_out, int out_size)
{
    const float* feature      = (const float*)d_in[0];
    const int*   ss           = (const int*)d_in[1];
    const int*   lsi          = (const int*)d_in[2];
    const float* inst_in      = (const float*)d_in[3];
    const float* anchor_in    = (const float*)d_in[4];
    const float* ti           = (const float*)d_in[5];
    const float* temp_inst    = (const float*)d_in[6];
    const float* temp_anchor  = (const float*)d_in[7];
    const unsigned char* mask = (const unsigned char*)d_in[8];
    const int*   track_id     = (const int*)d_in[9];
    const float* image_wh     = (const float*)d_in[10];
    const float* l2i          = (const float*)d_in[11];
    const float* anchor_w     = (const float*)d_in[12];
    const float* anchor_b     = (const float*)d_in[13];
    const float* kps_w        = (const float*)d_in[14];
    const float* kps_b        = (const float*)d_in[15];
    const float* wfc_w        = (const float*)d_in[16];
    const float* wfc_b        = (const float*)d_in[17];
    const float* outp_w       = (const float*)d_in[18];
    const float* outp_b       = (const float*)d_in[19];
    const float* ffn_w        = (const float*)d_in[20];
    const float* ffn_b        = (const float*)d_in[21];
    const float* reg_w        = (const float*)d_in[22];
    const float* reg_b        = (const float*)d_in[23];
    const float* cls_w        = (const float*)d_in[24];
    const float* cls_b        = (const float*)d_in[25];
    const float* qt_w         = (const float*)d_in[26];
    const float* qt_b         = (const float*)d_in[27];

    int T = in_sizes[0] / (NC*ED);
    float* out = (float*)d_out;

    static float *p_instA = nullptr, *p_instB = nullptr, *p_anchorA = nullptr,
                 *p_anchorB = nullptr, *p_Wcomb = nullptr, *p_bcomb = nullptr,
                 *p_AWm = nullptr;
    static bool init_done = false;
    if (!init_done) {
        cudaGetSymbolAddress((void**)&p_instA,   g_instA);
        cudaGetSymbolAddress((void**)&p_instB,   g_instB);
        cudaGetSymbolAddress((void**)&p_anchorA, g_anchorA);
        cudaGetSymbolAddress((void**)&p_anchorB, g_anchorB);
        cudaGetSymbolAddress((void**)&p_Wcomb,   g_Wcomb);
        cudaGetSymbolAddress((void**)&p_bcomb,   g_bcomb);
        cudaGetSymbolAddress((void**)&p_AWm,     g_AWm);
        cudaFuncSetAttribute(k5_fused, cudaFuncAttributeMaxDynamicSharedMemorySize, K5_SMEM);
        init_done = true;
    }

    kP1a<<<dim3(4,4,6), 256>>>(outp_w, ffn_w);
    kP1b<<<6, 256>>>(outp_b, ffn_w, ffn_b);
    kP2<<<dim3(26,6), 256>>>(anchor_w, anchor_b, wfc_w);

    for (int i = 0; i < NDEC; i++) {
        const float* instR = (i == 0) ? inst_in   : p_instB;
        float*       instW = (i == 0) ? p_instA   : p_instB;
        const float* anchR = (i == 0) ? anchor_in : p_anchorB;
        float*       anchW = (i == 0) ? p_anchorA : p_anchorB;

        dim3 g2(WTOT/BN, (NA + BM - 1)/BM);
        k2_wfc_gemm<<<g2, 256>>>(instR, anchR,
                                 wfc_w + (size_t)i*ED*WTOT,
                                 wfc_b + (size_t)i*WTOT,
                                 p_AWm + (size_t)i*12*WTOT);

        float* feats = out + OFF_TMP + (size_t)i*NA*ED;
        k4_daf<<<NA, 256>>>(feature, ss, lsi, T, feats, instR, anchR,
                            kps_w + (size_t)i*ED*NLEARN*3,
                            kps_b + (size_t)i*NLEARN*3,
                            l2i, image_wh);

        int cls_mode = (i == 0) ? 1 : ((i == NDEC-1) ? 2 : 0);
        int qt_on    = (i == NDEC-1) ? 1 : 0;
        k5_fused<<<NB5, 512, K5_SMEM>>>(feats,
                    p_Wcomb + (size_t)i*ED*ED,
                    p_bcomb + (size_t)i*ED,
                    ffn_w  + (size_t)i*2*ED*ED,
                    reg_w  + (size_t)i*ED*ADIM,  reg_b  + (size_t)i*ADIM,
                    cls_w  + (size_t)i*ED*NCLS,  cls_b  + (size_t)i*NCLS,
                    qt_w   + (size_t)i*ED,       qt_b   + (size_t)i,
                    ti, instR, instW, anchR, anchW,
                    cls_mode, out + OFF_CLS, qt_on, out + OFF_QT);

        if (i == 0) {
            k_rank<<<1, 1024>>>();
            k_gather<<<NA, 256>>>(temp_inst, temp_anchor, mask);
        }
    }

    k_finalize<<<(NA*ED + 255)/256, 256>>>(out, track_id, mask);
}

// round 16
// speedup vs baseline: 1.0322x; 1.0070x over previous
#include <cuda_runtime.h>
#include <cuda_bf16.h>
#include <math.h>

#define NA    900
#define NTEMP 600
#define ED    256
#define NC    6
#define NL    4
#define NP    13
#define NG    8
#define NLEARN 6
#define NDEC  6
#define ADIM  11
#define NCLS  10
#define WTOT  (NC*NL*NP*NG)   // 2496
#define NSEL  (NA-NTEMP)      // 300
#define NITEM (NL*NP*NC)      // 312
#define WSTR  313             // transposed softmax row stride

typedef unsigned long long ull;

// -------- output layout (flattened tuple, float32) --------
#define OFF_INST   0
#define OFF_ANCHOR (NA*ED)
#define OFF_CLS    (OFF_ANCHOR + NA*ADIM)
#define OFF_QT     (OFF_CLS + NA*NCLS)
#define OFF_TRACK  (OFF_QT + NA)
#define OFF_TMP    (OFF_TRACK + NA)

// -------- scratch --------
__device__ __align__(16) float g_instA[NA*ED];
__device__ __align__(16) float g_instB[NA*ED];
__device__ __align__(16) float g_anchorA[NA*ADIM];
__device__ __align__(16) float g_anchorB[NA*ADIM];
__device__ __align__(16) float g_W[NA*WTOT];
__device__ __align__(16) float g_cls[NA*NCLS];
__device__ __align__(16) float g_Wcomb[NDEC*ED*ED];
__device__ __align__(16) float g_bcomb[NDEC*ED];
__device__ __align__(16) float g_AWm[NDEC*12*WTOT];
__device__ int g_sel[NA];

__constant__ float c_FIX[7][3] = {
    {0.f,0.f,0.f},{0.5f,0.f,0.f},{-0.5f,0.f,0.f},
    {0.f,0.5f,0.f},{0.f,-0.5f,0.f},{0.f,0.f,0.5f},{0.f,0.f,-0.5f}};

// ---- f32x2 helpers ----
__device__ __forceinline__ ull pack2(float x, float y) {
    ull r;
    asm("mov.b64 %0, {%1, %2};" : "=l"(r) : "f"(x), "f"(y));
    return r;
}
__device__ __forceinline__ void unpack2(ull v, float& x, float& y) {
    asm("mov.b64 {%0, %1}, %2;" : "=f"(x), "=f"(y) : "l"(v));
}
__device__ __forceinline__ void ffma2(ull& acc, ull a, ull b) {
    asm("fma.rn.f32x2 %0, %1, %2, %0;" : "+l"(acc) : "l"(a), "l"(b));
}

// ===================== P1a: Wcomb = Wo @ Wf1 (per iter) ===================
__global__ void kP1a(const float* __restrict__ outp_w,
                     const float* __restrict__ ffn_w)
{
    int i = blockIdx.z;
    const float* A = outp_w + (size_t)i*ED*ED;
    const float* B = ffn_w + (size_t)i*2*ED*ED;
    float* C = g_Wcomb + (size_t)i*ED*ED;

    __shared__ __align__(16) float As[64][16];
    __shared__ __align__(16) float Bs[16][64];

    int tid = threadIdx.x;
    int tRow = tid >> 4, tCol = tid & 15;
    int m0 = blockIdx.y * 64, n0 = blockIdx.x * 64;
    int aRow = tid >> 2, aK4 = (tid & 3) * 4;
    int bRow = tid >> 4, bCol = (tid & 15) * 4;

    ull acc[4][2];
    #pragma unroll
    for (int r = 0; r < 4; r++) { acc[r][0] = 0ull; acc[r][1] = 0ull; }

    for (int k0 = 0; k0 < ED; k0 += 16) {
        *(float4*)&As[aRow][aK4] = *(const float4*)&A[(m0+aRow)*ED + k0 + aK4];
        *(float4*)&Bs[bRow][bCol] = *(const float4*)&B[(k0+bRow)*ED + n0 + bCol];
        __syncthreads();
        #pragma unroll
        for (int k = 0; k < 16; k++) {
            ull b0 = *(const ull*)&Bs[k][tCol*4 + 0];
            ull b1 = *(const ull*)&Bs[k][tCol*4 + 2];
            #pragma unroll
            for (int r = 0; r < 4; r++) {
                float a = As[tRow*4 + r][k];
                ull ad = pack2(a, a);
                ffma2(acc[r][0], ad, b0);
                ffma2(acc[r][1], ad, b1);
            }
        }
        __syncthreads();
    }
    #pragma unroll
    for (int r = 0; r < 4; r++) {
        float x0, y0, x1, y1;
        unpack2(acc[r][0], x0, y0);
        unpack2(acc[r][1], x1, y1);
        *(float4*)&C[(m0+tRow*4+r)*ED + n0 + tCol*4] = make_float4(x0, y0, x1, y1);
    }
}

// ===================== P1b: bcomb = bo@Wf1 + bf ===========================
__global__ void kP1b(const float* __restrict__ outp_b,
                     const float* __restrict__ ffn_w,
                     const float* __restrict__ ffn_b)
{
    int i = blockIdx.x;
    const float* bo = outp_b + (size_t)i*ED;
    const float* Wf = ffn_w + (size_t)i*2*ED*ED;
    const float* bf = ffn_b + (size_t)i*ED;
    int t = threadIdx.x;
    __shared__ float sbo[ED];
    sbo[t] = bo[t];
    __syncthreads();
    float s0 = 0.f, s1 = 0.f, s2 = 0.f, s3 = 0.f;
    for (int n = 0; n < ED; n += 4) {
        s0 += sbo[n+0] * Wf[(n+0)*ED + t];
        s1 += sbo[n+1] * Wf[(n+1)*ED + t];
        s2 += sbo[n+2] * Wf[(n+2)*ED + t];
        s3 += sbo[n+3] * Wf[(n+3)*ED + t];
    }
    g_bcomb[i*ED + t] = bf[t] + ((s0 + s1) + (s2 + s3));
}

// ===================== P2: AWm = [anchor_w;anchor_b] @ wfc ================
__global__ void kP2(const float* __restrict__ anchor_w,
                    const float* __restrict__ anchor_b,
                    const float* __restrict__ wfc_w)
{
    int i = blockIdx.y;
    int n0 = blockIdx.x * 96;
    const float* Wm = wfc_w + (size_t)i*ED*WTOT;
    float* dst = g_AWm + (size_t)i*12*WTOT;
    int t = threadIdx.x;

    __shared__ float sAw[12*ED];
    __shared__ float sT[32*96];

    for (int idx = t; idx < 11*ED; idx += 256) sAw[idx] = anchor_w[idx];
    for (int idx = t; idx < ED; idx += 256)    sAw[11*ED + idx] = anchor_b[idx];
    __syncthreads();

    float acc[5] = {0.f,0.f,0.f,0.f,0.f};
    for (int k0 = 0; k0 < ED; k0 += 32) {
        for (int idx = t; idx < 32*96; idx += 256) {
            int kk = idx / 96, nc = idx % 96;
            sT[idx] = Wm[(size_t)(k0+kk)*WTOT + n0 + nc];
        }
        __syncthreads();
        int slot = 0;
        for (int o = t; o < 12*96; o += 256, slot++) {
            int j = o / 96, nc = o % 96;
            float s = acc[slot];
            #pragma unroll 8
            for (int kk = 0; kk < 32; kk++)
                s += sAw[j*ED + k0 + kk] * sT[kk*96 + nc];
            acc[slot] = s;
        }
        __syncthreads();
    }
    int slot = 0;
    for (int o = t; o < 12*96; o += 256, slot++) {
        int j = o / 96, nc = o % 96;
        dst[(size_t)j*WTOT + n0 + nc] = acc[slot];
    }
}

// ===================== k2: wfc GEMM + rank-12 fold (k-major A) ============
#define BM 64
#define BMS 68     // k-major row stride (multiple of 4 for float4 reads)
#define BN 96
#define BK 16
__global__ void k2_wfc_gemm(const float* __restrict__ instR,
                            const float* __restrict__ anchR,
                            const float* __restrict__ Wm,
                            const float* __restrict__ bias,
                            const float* __restrict__ AWm)
{
    __shared__ __align__(16) float As[BK][BMS];  // k-major: rows contiguous
    __shared__ __align__(16) float Bs[BK][BN];
    __shared__ float sAnchT[BM][12];
    __shared__ __align__(8) float sAW[12][BN];

    int tid  = threadIdx.x;
    int tRow = tid >> 4, tCol = tid & 15;
    int m0 = blockIdx.y * BM, n0 = blockIdx.x * BN;

    for (int idx = tid; idx < BM*ADIM; idx += 256) {
        int r = idx / ADIM, j = idx % ADIM;
        int row = m0 + r;
        sAnchT[r][j] = (row < NA) ? anchR[row*ADIM + j] : 0.f;
    }
    for (int idx = tid; idx < 12*BN; idx += 256) {
        int j = idx / BN, nc = idx % BN;
        sAW[j][nc] = AWm[(size_t)j*WTOT + n0 + nc];
    }

    ull acc[4][3];
    #pragma unroll
    for (int i = 0; i < 4; i++)
        #pragma unroll
        for (int j = 0; j < 3; j++) acc[i][j] = 0ull;

    int aRow = tid >> 2;
    int aK4  = (tid & 3) * 4;
    int gm   = m0 + aRow;
    bool mok = (gm < NA);

    int bR[3], bC[3];
    #pragma unroll
    for (int it = 0; it < 3; it++) {
        int lin = tid + it*256;
        bR[it] = lin / 48;
        bC[it] = (lin % 48) * 2;
    }

    float4 avr = mok ? *(const float4*)&instR[gm*ED + aK4] : make_float4(0.f,0.f,0.f,0.f);
    float2 bvr[3];
    #pragma unroll
    for (int it = 0; it < 3; it++)
        bvr[it] = *(const float2*)&Wm[(size_t)bR[it]*WTOT + n0 + bC[it]];

    for (int k0 = 0; k0 < ED; k0 += BK) {
        // transpose-store A tile (4 STS.32, ~2-way conflicts, once per tile)
        As[aK4+0][aRow] = avr.x;
        As[aK4+1][aRow] = avr.y;
        As[aK4+2][aRow] = avr.z;
        As[aK4+3][aRow] = avr.w;
        #pragma unroll
        for (int it = 0; it < 3; it++)
            *(float2*)&Bs[bR[it]][bC[it]] = bvr[it];
        __syncthreads();

        int k0n = k0 + BK;
        if (k0n < ED) {
            if (mok) avr = *(const float4*)&instR[gm*ED + k0n + aK4];
            #pragma unroll
            for (int it = 0; it < 3; it++)
                bvr[it] = *(const float2*)&Wm[(size_t)(k0n + bR[it])*WTOT + n0 + bC[it]];
        }

        #pragma unroll
        for (int k = 0; k < BK; k++) {
            ull b0 = *(const ull*)&Bs[k][tCol*6 + 0];
            ull b1 = *(const ull*)&Bs[k][tCol*6 + 2];
            ull b2 = *(const ull*)&Bs[k][tCol*6 + 4];
            float4 a4 = *(const float4*)&As[k][tRow*4];   // 1 broadcast LDS.128
            float ar[4] = {a4.x, a4.y, a4.z, a4.w};
            #pragma unroll
            for (int i = 0; i < 4; i++) {
                ull ad = pack2(ar[i], ar[i]);
                ffma2(acc[i][0], ad, b0);
                ffma2(acc[i][1], ad, b1);
                ffma2(acc[i][2], ad, b2);
            }
        }
        __syncthreads();
    }

    float2 bb[3];
    #pragma unroll
    for (int j = 0; j < 3; j++)
        bb[j] = *(const float2*)&bias[n0 + tCol*6 + 2*j];

    #pragma unroll
    for (int i = 0; i < 4; i++) {
        int lr = tRow*4 + i;
        int r = m0 + lr;
        if (r >= NA) continue;
        ull corr[3];
        #pragma unroll
        for (int j = 0; j < 3; j++)
            corr[j] = *(const ull*)&sAW[11][tCol*6 + 2*j];
        #pragma unroll
        for (int j = 0; j < ADIM; j++) {
            float a = sAnchT[lr][j];
            ull ad = pack2(a, a);
            ffma2(corr[0], ad, *(const ull*)&sAW[j][tCol*6 + 0]);
            ffma2(corr[1], ad, *(const ull*)&sAW[j][tCol*6 + 2]);
            ffma2(corr[2], ad, *(const ull*)&sAW[j][tCol*6 + 4]);
        }
        #pragma unroll
        for (int j = 0; j < 3; j++) {
            float x, y, cx, cy;
            unpack2(acc[i][j], x, y);
            unpack2(corr[j], cx, cy);
            float2 v = make_float2(x + cx + bb[j].x, y + cy + bb[j].y);
            *(float2*)&g_W[(size_t)r*WTOT + n0 + tCol*6 + 2*j] = v;
        }
    }
}

// ===================== k4: kps/proj + softmax + chunked aggregation =======
__global__ void k4_daf(const float* __restrict__ feature,
                       const int* __restrict__ ss,
                       const int* __restrict__ lsi,
                       int T,
                       float* __restrict__ feats_out,
                       const float* __restrict__ instR,
                       const float* __restrict__ anchR,
                       const float* __restrict__ kps_w,
                       const float* __restrict__ kps_b,
                       const float* __restrict__ l2i,
                       const float* __restrict__ image_wh)
{
    int a = blockIdx.x, t = threadIdx.x, g8 = t >> 5, lane = t & 31;

    __shared__ float sWt[NG*WSTR];
    __shared__ float sfeat[ED];
    __shared__ float sanchor[ADIM];
    __shared__ float spart[18][8];
    __shared__ float slearn[18];
    __shared__ float skp[NP][3];
    __shared__ float suv[NP*NC*2];
    __shared__ int   sh[12];
    __shared__ int   sValid[NITEM];
    __shared__ int   sWi[NITEM];
    __shared__ int4  sOff[NITEM];
    __shared__ float4 sCw[NITEM];
    __shared__ short sIdx[NITEM];
    __shared__ int   s_nv;
    __shared__ __align__(16) float4 sPart[4][64];

    for (int idx = t; idx < WTOT; idx += 256) {
        float v = g_W[(size_t)a*WTOT + idx];
        sWt[(idx & 7)*WSTR + (idx >> 3)] = v;
    }
    sfeat[t] = instR[a*ED + t];
    if (t < ADIM) sanchor[t] = anchR[a*ADIM + t];
    if (t < 8) sh[t]   = ss[t];
    if (t < 4) sh[8+t] = lsi[t];
    __syncthreads();

    {
        float* row = &sWt[g8*WSTR];
        float vals[10];
        float mx = -1e30f;
        int cnt = 0;
        for (int j = lane; j < NITEM; j += 32) {
            float v = row[j];
            vals[cnt++] = v;
            mx = fmaxf(mx, v);
        }
        #pragma unroll
        for (int o = 16; o; o >>= 1) mx = fmaxf(mx, __shfl_xor_sync(0xffffffffu, mx, o));
        float sum = 0.f;
        for (int i = 0; i < cnt; i++) { vals[i] = __expf(vals[i] - mx); sum += vals[i]; }
        #pragma unroll
        for (int o = 16; o; o >>= 1) sum += __shfl_xor_sync(0xffffffffu, sum, o);
        float inv = 1.f / sum;
        cnt = 0;
        for (int j = lane; j < NITEM; j += 32) row[j] = vals[cnt++] * inv;
    }

    if (t < 144) {
        int m = t >> 3, seg = t & 7;
        float s = 0.f;
        int k0 = seg * 32;
        #pragma unroll 8
        for (int k = k0; k < k0+32; k++) s += sfeat[k] * kps_w[k*18 + m];
        spart[m][seg] = s;
    }
    __syncthreads();
    if (t < 18) {
        float s = kps_b[t];
        #pragma unroll
        for (int seg = 0; seg < 8; seg++) s += spart[t][seg];
        slearn[t] = s;
    }
    __syncthreads();

    if (t < NP*3) {
        int p = t/3, d = t%3;
        float center = sanchor[d];
        float size   = expf(sanchor[3+d]);
        float v = (p < 7) ? c_FIX[p][d] : slearn[(p-7)*3 + d];
        skp[p][d] = center + v * size;
    }
    __syncthreads();

    if (t < NP*NC) {
        int p = t / NC, c = t % NC;
        const float* L = &l2i[c*16];
        float kx = skp[p][0], ky = skp[p][1], kz = skp[p][2];
        float p0 = L[0]*kx + L[1]*ky + L[2]*kz  + L[3];
        float p1 = L[4]*kx + L[5]*ky + L[6]*kz  + L[7];
        float p2 = L[8]*kx + L[9]*ky + L[10]*kz + L[11];
        float z  = fmaxf(p2, 1e-5f);
        suv[(p*NC + c)*2 + 0] = p0 / z / image_wh[c*2 + 0];
        suv[(p*NC + c)*2 + 1] = p1 / z / image_wh[c*2 + 1];
    }
    __syncthreads();

    for (int i = t; i < NITEM; i += 256) {
        int c  = i % NC;
        int lp = i / NC;
        int p  = lp % NP;
        int l  = lp / NP;
        int H = sh[l*2], Wd = sh[l*2+1], st = sh[8+l];
        float fH = (float)H, fW = (float)Wd;
        float u = suv[(p*NC + c)*2 + 0];
        float v = suv[(p*NC + c)*2 + 1];
        float x = u*fW - 0.5f, y = v*fH - 0.5f;
        float x0f = floorf(x), y0f = floorf(y);
        float dx = x - x0f, dy = y - y0f;
        float x1f = x0f + 1.f, y1f = y0f + 1.f;
        bool vx0 = (x0f >= 0.f) && (x0f < fW);
        bool vx1 = (x1f >= 0.f) && (x1f < fW);
        bool vy0 = (y0f >= 0.f) && (y0f < fH);
        bool vy1 = (y1f >= 0.f) && (y1f < fH);
        int x0 = vx0 ? (int)x0f : 0;
        int x1 = vx1 ? (int)x1f : 0;
        int y0 = vy0 ? (int)y0f : 0;
        int y1 = vy1 ? (int)y1f : 0;

        float4 w;
        w.x = (vx0 && vy0) ? (1.f-dx)*(1.f-dy) : 0.f;
        w.y = (vx1 && vy0) ? dx*(1.f-dy)       : 0.f;
        w.z = (vx0 && vy1) ? (1.f-dx)*dy       : 0.f;
        w.w = (vx1 && vy1) ? dx*dy             : 0.f;

        int base = (c*T + st)*ED;
        int4 o;
        o.x = (base + (y0*Wd + x0)*ED) >> 2;
        o.y = (base + (y0*Wd + x1)*ED) >> 2;
        o.z = (base + (y1*Wd + x0)*ED) >> 2;
        o.w = (base + (y1*Wd + x1)*ED) >> 2;

        sValid[i] = ((w.x != 0.f) | (w.y != 0.f) | (w.z != 0.f) | (w.w != 0.f)) ? 1 : 0;
        sWi[i]    = c*52 + l*13 + p;
        sOff[i]   = o;
        sCw[i]    = w;
    }
    __syncthreads();

    if (t < 32) {
        const int CH = (NITEM + 31) / 32;
        int start = t * CH;
        int end = start + CH; if (end > NITEM) end = NITEM;
        int cnt = 0;
        for (int i = start; i < end; i++) cnt += sValid[i];
        int x = cnt;
        #pragma unroll
        for (int o = 1; o < 32; o <<= 1) {
            int y = __shfl_up_sync(0xffffffffu, x, o);
            if (t >= o) x += y;
        }
        int pos = x - cnt;
        for (int i = start; i < end; i++)
            if (sValid[i]) sIdx[pos++] = (short)i;
        if (t == 31) s_nv = x;
    }
    __syncthreads();

    {
        int chunk = t >> 6;
        int ch = t & 63;
        int g = ch >> 3;
        const float4* fb = (const float4*)feature;
        int nv = s_nv;
        ull acc01 = 0ull, acc23 = 0ull;
        for (int ii = chunk; ii < nv; ii += 4) {
            int i = sIdx[ii];
            float aw = sWt[g*WSTR + sWi[i]];
            float4 w = sCw[i];
            int4  o = sOff[i];
            if (w.x != 0.f) {
                float4 f = fb[o.x + ch];
                float wc = w.x * aw; ull wd = pack2(wc, wc);
                ffma2(acc01, wd, pack2(f.x, f.y));
                ffma2(acc23, wd, pack2(f.z, f.w));
            }
            if (w.y != 0.f) {
                float4 f = fb[o.y + ch];
                float wc = w.y * aw; ull wd = pack2(wc, wc);
                ffma2(acc01, wd, pack2(f.x, f.y));
                ffma2(acc23, wd, pack2(f.z, f.w));
            }
            if (w.z != 0.f) {
                float4 f = fb[o.z + ch];
                float wc = w.z * aw; ull wd = pack2(wc, wc);
                ffma2(acc01, wd, pack2(f.x, f.y));
                ffma2(acc23, wd, pack2(f.z, f.w));
            }
            if (w.w != 0.f) {
                float4 f = fb[o.w + ch];
                float wc = w.w * aw; ull wd = pack2(wc, wc);
                ffma2(acc01, wd, pack2(f.x, f.y));
                ffma2(acc23, wd, pack2(f.z, f.w));
            }
        }
        float4 r;
        unpack2(acc01, r.x, r.y);
        unpack2(acc23, r.z, r.w);
        sPart[chunk][ch] = r;
    }
    __syncthreads();
    if (t < 64) {
        float4 p0 = sPart[0][t], p1 = sPart[1][t], p2 = sPart[2][t], p3 = sPart[3][t];
        float4 r;
        r.x = ((p0.x + p1.x) + p2.x) + p3.x;
        r.y = ((p0.y + p1.y) + p2.y) + p3.y;
        r.z = ((p0.z + p1.z) + p2.z) + p3.z;
        r.w = ((p0.w + p1.w) + p2.w) + p3.w;
        *(float4*)&feats_out[a*ED + t*4] = r;
    }
}

// ===================== k5: split-K ffn + heads (ping-pong, dyn smem) ======
#define FM 16
#define NB5 ((NA + FM - 1) / FM)   // 57
#define K5_FLOATS (4096 + 4096 + 4096 + 4096 + 4096)
#define K5_SMEM (K5_FLOATS*4)      // 80 KB
__global__ void __launch_bounds__(512, 1)
k5_fused(const float* __restrict__ feats,
         const float* __restrict__ Wc,
         const float* __restrict__ bc,
         const float* __restrict__ Wf,
         const float* __restrict__ reg_w,  const float* __restrict__ reg_b,
         const float* __restrict__ cls_w,  const float* __restrict__ cls_b,
         const float* __restrict__ qt_w,   const float* __restrict__ qt_b,
         const float* __restrict__ time_interval,
         const float* __restrict__ instR, float* __restrict__ instW,
         const float* __restrict__ anchR, float* __restrict__ anchW,
         int cls_mode, float* cls_dst,
         int qt_on, float* qt_dst)
{
    extern __shared__ __align__(16) float smem5[];
    float* sA  = smem5;
    float* sI  = sA + 4096;
    float* sU0 = sI + 4096;
    float* sU1 = sU0 + 4096;
    float* sP  = sU1 + 4096;

    int t = threadIdx.x;
    int g = t >> 8;
    int tt = t & 255;
    int tRow = tt >> 6;
    int tCol = tt & 63;
    int r0 = blockIdx.x * FM;

    for (int idx = t; idx < FM*256; idx += 512) {
        int r = idx >> 8, c = idx & 255;
        int row = r0 + r;
        sA[idx] = (row < NA) ? feats[row*ED + c] : 0.f;
        sI[idx] = (row < NA) ? instR[row*ED + c] : 0.f;
    }
    __syncthreads();

    const float* Wg = (g == 0) ? Wc : (Wf + ED*ED);
    float* sUg = (g == 0) ? sU0 : sU1;
    const float* sXg = (g == 0) ? sA : sI;
    int lr0 = tt >> 6, lc0 = tt & 63;

    ull acc[4][2];
    #pragma unroll
    for (int i = 0; i < 4; i++) { acc[i][0] = 0ull; acc[i][1] = 0ull; }

    float4 bv0 = *(const float4*)&Wg[(lr0)*ED + lc0*4];
    float4 bv1 = *(const float4*)&Wg[(lr0+4)*ED + lc0*4];

    for (int kt = 0; kt < 32; kt++) {
        float* buf = sUg + (kt & 1) * 2048;
        *(float4*)&buf[lr0*256 + lc0*4]     = bv0;
        *(float4*)&buf[(lr0+4)*256 + lc0*4] = bv1;
        __syncthreads();
        if (kt + 1 < 32) {
            bv0 = *(const float4*)&Wg[((kt+1)*8 + lr0)*ED + lc0*4];
            bv1 = *(const float4*)&Wg[((kt+1)*8 + lr0+4)*ED + lc0*4];
        }
        #pragma unroll
        for (int k = 0; k < 8; k++) {
            ull b0 = *(const ull*)&buf[k*256 + tCol*4];
            ull b1 = *(const ull*)&buf[k*256 + tCol*4 + 2];
            int kk = kt*8 + k;
            #pragma unroll
            for (int i = 0; i < 4; i++) {
                float a = sXg[(tRow*4 + i)*256 + kk];
                ull ad = pack2(a, a);
                ffma2(acc[i][0], ad, b0);
                ffma2(acc[i][1], ad, b1);
            }
        }
    }
    __syncthreads();

    if (g == 1) {
        #pragma unroll
        for (int i = 0; i < 4; i++) {
            float x0, y0, x1, y1;
            unpack2(acc[i][0], x0, y0);
            unpack2(acc[i][1], x1, y1);
            *(float4*)&sP[(tRow*4 + i)*256 + tCol*4] = make_float4(x0, y0, x1, y1);
        }
    }
    __syncthreads();

    if (g == 0) {
        float4 bc4 = *(const float4*)&bc[tCol*4];
        #pragma unroll
        for (int i = 0; i < 4; i++) {
            float x0, y0, x1, y1;
            unpack2(acc[i][0], x0, y0);
            unpack2(acc[i][1], x1, y1);
            float4 p = *(const float4*)&sP[(tRow*4 + i)*256 + tCol*4];
            float nv0 = fmaxf(x0 + p.x + bc4.x, 0.f);
            float nv1 = fmaxf(y0 + p.y + bc4.y, 0.f);
            float nv2 = fmaxf(x1 + p.z + bc4.z, 0.f);
            float nv3 = fmaxf(y1 + p.w + bc4.w, 0.f);
            int row = r0 + tRow*4 + i;
            if (row < NA)
                *(float4*)&instW[row*ED + tCol*4] = make_float4(nv0, nv1, nv2, nv3);
            int rr = tRow*4 + i;
            sI[(tCol*4 + 0)*16 + rr] = nv0;
            sI[(tCol*4 + 1)*16 + rr] = nv1;
            sI[(tCol*4 + 2)*16 + rr] = nv2;
            sI[(tCol*4 + 3)*16 + rr] = nv3;
        }
    }
    __syncthreads();

    bool do_cls = (cls_mode != 0);
    for (int idx = t; idx < ED*ADIM; idx += 512) sA[idx] = reg_w[idx];
    if (do_cls)
        for (int idx = t; idx < ED*NCLS; idx += 512) sP[idx] = cls_w[idx];
    if (qt_on)
        for (int idx = t; idx < ED; idx += 512) sA[ED*ADIM + idx] = qt_w[idx];
    __syncthreads();

    float ti = time_interval[0];
    for (int o = t; o < FM*ADIM; o += 512) {
        int r = o / ADIM, j = o % ADIM;
        int row = r0 + r;
        if (row < NA) {
            float s0 = 0.f, s1 = 0.f, s2 = 0.f, s3 = 0.f;
            for (int k = 0; k < ED; k += 4) {
                s0 += sI[(k+0)*16 + r] * sA[(k+0)*ADIM + j];
                s1 += sI[(k+1)*16 + r] * sA[(k+1)*ADIM + j];
                s2 += sI[(k+2)*16 + r] * sA[(k+2)*ADIM + j];
                s3 += sI[(k+3)*16 + r] * sA[(k+3)*ADIM + j];
            }
            float s = reg_b[j] + ((s0 + s1) + (s2 + s3));
            if (j >= 8) s /= ti;
            anchW[row*ADIM + j] = anchR[row*ADIM + j] + s;
        }
    }
    if (do_cls) {
        float* cdst = (cls_mode == 1) ? g_cls : cls_dst;
        for (int o = t; o < FM*NCLS; o += 512) {
            int r = o / NCLS, j = o % NCLS;
            int row = r0 + r;
            if (row < NA) {
                float s0 = 0.f, s1 = 0.f, s2 = 0.f, s3 = 0.f;
                for (int k = 0; k < ED; k += 4) {
                    s0 += sI[(k+0)*16 + r] * sP[(k+0)*NCLS + j];
                    s1 += sI[(k+1)*16 + r] * sP[(k+1)*NCLS + j];
                    s2 += sI[(k+2)*16 + r] * sP[(k+2)*NCLS + j];
                    s3 += sI[(k+3)*16 + r] * sP[(k+3)*NCLS + j];
                }
                cdst[row*NCLS + j] = cls_b[j] + ((s0 + s1) + (s2 + s3));
            }
        }
    }
    if (qt_on) {
        for (int o = t; o < FM; o += 512) {
            int row = r0 + o;
            if (row < NA) {
                float s0 = 0.f, s1 = 0.f, s2 = 0.f, s3 = 0.f;
                for (int k = 0; k < ED; k += 4) {
                    s0 += sI[(k+0)*16 + o] * sA[ED*ADIM + k+0];
                    s1 += sI[(k+1)*16 + o] * sA[ED*ADIM + k+1];
                    s2 += sI[(k+2)*16 + o] * sA[ED*ADIM + k+2];
                    s3 += sI[(k+3)*16 + o] * sA[ED*ADIM + k+3];
                }
                qt_dst[row] = qt_b[0] + ((s0 + s1) + (s2 + s3));
            }
        }
    }
}

// ===================== rank + gather ===============
__global__ void k_rank()
{
    __shared__ float ssc[NA];
    int t = threadIdx.x;
    if (t < NA) {
        float m = -1e30f;
        #pragma unroll
        for (int j = 0; j < NCLS; j++) m = fmaxf(m, g_cls[t*NCLS + j]);
        ssc[t] = m;
    }
    __syncthreads();
    if (t < NA) {
        float sc = ssc[t];
        int cnt = 0;
        for (int b = 0; b < NA; b++) {
            float sb = ssc[b];
            cnt += (sb > sc) || (sb == sc && b < t);
        }
        if (cnt < NSEL) g_sel[NTEMP + cnt] = t;
    }
}

__global__ void k_gather(const float* __restrict__ temp_inst,
                         const float* __restrict__ temp_anchor,
                         const unsigned char* __restrict__ mask)
{
    int r = blockIdx.x, t = threadIdx.x;
    bool m = mask[0] != 0;
    if (m) {
        if (r < NTEMP) {
            g_instB[r*ED + t] = temp_inst[r*ED + t];
            if (t < ADIM) g_anchorB[r*ADIM + t] = temp_anchor[r*ADIM + t];
        } else {
            int s = g_sel[r];
            g_instB[r*ED + t] = g_instA[s*ED + t];
            if (t < ADIM) g_anchorB[r*ADIM + t] = g_anchorA[s*ADIM + t];
        }
    } else {
        g_instB[r*ED + t] = g_instA[r*ED + t];
        if (t < ADIM) g_anchorB[r*ADIM + t] = g_anchorA[r*ADIM + t];
    }
}

// ===================== finalize ===========================================
__global__ void k_finalize(float* __restrict__ out,
                           const int* __restrict__ track_id,
                           const unsigned char* __restrict__ mask)
{
    int i = blockIdx.x*blockDim.x + threadIdx.x;
    if (i < NA*ED)   out[OFF_INST + i]   = g_instB[i];
    if (i < NA*ADIM) out[OFF_ANCHOR + i] = g_anchorB[i];
    if (i < NA) {
        bool m = mask[0] != 0;
        out[OFF_TRACK + i] = m ? (float)track_id[i] : -1.0f;
    }
}

// ===================== host ===============================================
extern "C" void kernel_launch(void* const* d_in, const int* in_sizes, int n_in,
                              void* d_out, int out_size)
{
    const float* feature      = (const float*)d_in[0];
    const int*   ss           = (const int*)d_in[1];
    const int*   lsi          = (const int*)d_in[2];
    const float* inst_in      = (const float*)d_in[3];
    const float* anchor_in    = (const float*)d_in[4];
    const float* ti           = (const float*)d_in[5];
    const float* temp_inst    = (const float*)d_in[6];
    const float* temp_anchor  = (const float*)d_in[7];
    const unsigned char* mask = (const unsigned char*)d_in[8];
    const int*   track_id     = (const int*)d_in[9];
    const float* image_wh     = (const float*)d_in[10];
    const float* l2i          = (const float*)d_in[11];
    const float* anchor_w     = (const float*)d_in[12];
    const float* anchor_b     = (const float*)d_in[13];
    const float* kps_w        = (const float*)d_in[14];
    const float* kps_b        = (const float*)d_in[15];
    const float* wfc_w        = (const float*)d_in[16];
    const float* wfc_b        = (const float*)d_in[17];
    const float* outp_w       = (const float*)d_in[18];
    const float* outp_b       = (const float*)d_in[19];
    const float* ffn_w        = (const float*)d_in[20];
    const float* ffn_b        = (const float*)d_in[21];
    const float* reg_w        = (const float*)d_in[22];
    const float* reg_b        = (const float*)d_in[23];
    const float* cls_w        = (const float*)d_in[24];
    const float* cls_b        = (const float*)d_in[25];
    const float* qt_w         = (const float*)d_in[26];
    const float* qt_b         = (const float*)d_in[27];

    int T = in_sizes[0] / (NC*ED);
    float* out = (float*)d_out;

    static float *p_instA = nullptr, *p_instB = nullptr, *p_anchorA = nullptr,
                 *p_anchorB = nullptr, *p_Wcomb = nullptr, *p_bcomb = nullptr,
                 *p_AWm = nullptr;
    static bool init_done = false;
    if (!init_done) {
        cudaGetSymbolAddress((void**)&p_instA,   g_instA);
        cudaGetSymbolAddress((void**)&p_instB,   g_instB);
        cudaGetSymbolAddress((void**)&p_anchorA, g_anchorA);
        cudaGetSymbolAddress((void**)&p_anchorB, g_anchorB);
        cudaGetSymbolAddress((void**)&p_Wcomb,   g_Wcomb);
        cudaGetSymbolAddress((void**)&p_bcomb,   g_bcomb);
        cudaGetSymbolAddress((void**)&p_AWm,     g_AWm);
        cudaFuncSetAttribute(k5_fused, cudaFuncAttributeMaxDynamicSharedMemorySize, K5_SMEM);
        init_done = true;
    }

    kP1a<<<dim3(4,4,6), 256>>>(outp_w, ffn_w);
    kP1b<<<6, 256>>>(outp_b, ffn_w, ffn_b);
    kP2<<<dim3(26,6), 256>>>(anchor_w, anchor_b, wfc_w);

    for (int i = 0; i < NDEC; i++) {
        const float* instR = (i == 0) ? inst_in   : p_instB;
        float*       instW = (i == 0) ? p_instA   : p_instB;
        const float* anchR = (i == 0) ? anchor_in : p_anchorB;
        float*       anchW = (i == 0) ? p_anchorA : p_anchorB;

        dim3 g2(WTOT/BN, (NA + BM - 1)/BM);
        k2_wfc_gemm<<<g2, 256>>>(instR, anchR,
                                 wfc_w + (size_t)i*ED*WTOT,
                                 wfc_b + (size_t)i*WTOT,
                                 p_AWm + (size_t)i*12*WTOT);

        float* feats = out + OFF_TMP + (size_t)i*NA*ED;
        k4_daf<<<NA, 256>>>(feature, ss, lsi, T, feats, instR, anchR,
                            kps_w + (size_t)i*ED*NLEARN*3,
                            kps_b + (size_t)i*NLEARN*3,
                            l2i, image_wh);

        int cls_mode = (i == 0) ? 1 : ((i == NDEC-1) ? 2 : 0);
        int qt_on    = (i == NDEC-1) ? 1 : 0;
        k5_fused<<<NB5, 512, K5_SMEM>>>(feats,
                    p_Wcomb + (size_t)i*ED*ED,
                    p_bcomb + (size_t)i*ED,
                    ffn_w  + (size_t)i*2*ED*ED,
                    reg_w  + (size_t)i*ED*ADIM,  reg_b  + (size_t)i*ADIM,
                    cls_w  + (size_t)i*ED*NCLS,  cls_b  + (size_t)i*NCLS,
                    qt_w   + (size_t)i*ED,       qt_b   + (size_t)i,
                    ti, instR, instW, anchR, anchW,
                    cls_mode, out + OFF_CLS, qt_on, out + OFF_QT);

        if (i == 0) {
            k_rank<<<1, 1024>>>();
            k_gather<<<NA, 256>>>(temp_inst, temp_anchor, mask);
        }
    }

    k_finalize<<<(NA*ED + 255)/256, 256>>>(out, track_id, mask);
}